// round 2
// baseline (speedup 1.0000x reference)
#include <cuda_runtime.h>
#include <math.h>

#define PI_D 3.14159265358979323846

// ----------------------------- scratch (device globals) -----------------------------
__device__ float2 g_S [32*200*400];   // row-FFT'd field, compact rows, full cols
__device__ float2 g_S2[32*200*400];   // after column FFT * trans * IFFT, compact rows
__device__ float  g_I [32*200*200];   // final intensity, logical layout
__device__ float  g_pool[625*32];     // pooled [p][b]
__device__ float  g_W1T[625*512];     // W1 transposed [p][hh]
__device__ float  g_R1[512];          // row sums of W1
__device__ float2 g_w400[400];        // e^{-2*pi*i*k/400}, fp64-initialized

// ----------------------------- complex helpers -----------------------------
__device__ __forceinline__ float2 cmul(float2 a, float2 b){
    return make_float2(fmaf(a.x,b.x,-a.y*b.y), fmaf(a.x,b.y, a.y*b.x));
}
__device__ __forceinline__ float2 cfma(float2 r, float2 a, float2 w){
    r.x = fmaf(a.x,w.x, fmaf(-a.y,w.y,r.x));
    r.y = fmaf(a.x,w.y, fmaf( a.y,w.x,r.y));
    return r;
}
template<bool INV>
__device__ __forceinline__ float2 TW(int m){   // W400^m (conj if INV)
    float2 v = g_w400[m];
    if (INV) v.y = -v.y;
    return v;
}

// ----------------------------- FFT-20 (registers): n=20, j=5*j1+j2, k=k1+4*k2 -----------------------------
template<bool INV>
__device__ __forceinline__ void fft20(float2* a){
    float2 t[20];
    #pragma unroll
    for (int j2=0;j2<5;j2++){
        float2 x0=a[j2], x1=a[5+j2], x2=a[10+j2], x3=a[15+j2];
        float2 s02=make_float2(x0.x+x2.x, x0.y+x2.y);
        float2 d02=make_float2(x0.x-x2.x, x0.y-x2.y);
        float2 s13=make_float2(x1.x+x3.x, x1.y+x3.y);
        float2 d13=make_float2(x1.x-x3.x, x1.y-x3.y);
        float2 y0=make_float2(s02.x+s13.x, s02.y+s13.y);
        float2 y2=make_float2(s02.x-s13.x, s02.y-s13.y);
        float2 y1,y3;
        if (!INV){ y1=make_float2(d02.x+d13.y, d02.y-d13.x);   // d02 - i*d13
                   y3=make_float2(d02.x-d13.y, d02.y+d13.x); } // d02 + i*d13
        else     { y1=make_float2(d02.x-d13.y, d02.y+d13.x);
                   y3=make_float2(d02.x+d13.y, d02.y-d13.x); }
        t[j2]    = y0;                                   // W20^m = W400^{20m}
        t[5+j2]  = cmul(y1, TW<INV>(20*j2));
        t[10+j2] = cmul(y2, TW<INV>(40*j2));
        t[15+j2] = cmul(y3, TW<INV>(60*j2));
    }
    const float C1f= 0.30901699437494742f, S1f=0.95105651629515357f;
    const float C2f=-0.80901699437494745f, S2f=0.58778525229247313f;
    const float si = INV ? 1.f : -1.f;
    const float2 w1=make_float2(C1f, si*S1f), w2=make_float2(C2f, si*S2f);
    const float2 w3=make_float2(C2f,-si*S2f), w4=make_float2(C1f,-si*S1f);
    #pragma unroll
    for (int k1=0;k1<4;k1++){
        float2 b0=t[k1*5], b1=t[k1*5+1], b2=t[k1*5+2], b3=t[k1*5+3], b4=t[k1*5+4];
        float2 y0=make_float2(b0.x+b1.x+b2.x+b3.x+b4.x, b0.y+b1.y+b2.y+b3.y+b4.y);
        float2 y1=b0; y1=cfma(y1,b1,w1); y1=cfma(y1,b2,w2); y1=cfma(y1,b3,w3); y1=cfma(y1,b4,w4);
        float2 y2=b0; y2=cfma(y2,b1,w2); y2=cfma(y2,b2,w4); y2=cfma(y2,b3,w1); y2=cfma(y2,b4,w3);
        float2 y3=b0; y3=cfma(y3,b1,w3); y3=cfma(y3,b2,w1); y3=cfma(y3,b3,w4); y3=cfma(y3,b4,w2);
        float2 y4=b0; y4=cfma(y4,b1,w4); y4=cfma(y4,b2,w3); y4=cfma(y4,b3,w2); y4=cfma(y4,b4,w1);
        a[k1]=y0; a[k1+4]=y1; a[k1+8]=y2; a[k1+12]=y3; a[k1+16]=y4;
    }
}

// ----------------------------- FFT-400 (warp, 20 active lanes): 20x20 four-step -----------------------------
template<bool INV>
__device__ void fft400(float2* __restrict__ lin, float2* __restrict__ tmp, int lane){
    __syncwarp();
    float2 r[20];
    if (lane < 20){
        #pragma unroll
        for (int j1=0;j1<20;j1++) r[j1]=lin[j1*20+lane];
        fft20<INV>(r);                                   // over j1
        #pragma unroll
        for (int k1=1;k1<20;k1++) r[k1]=cmul(r[k1], TW<INV>(lane*k1));  // W400^{j2*k1}
        #pragma unroll
        for (int k1=0;k1<20;k1++) tmp[k1*21+lane]=r[k1];
    }
    __syncwarp();
    if (lane < 20){
        #pragma unroll
        for (int j2=0;j2<20;j2++) r[j2]=tmp[lane*21+j2];
        fft20<INV>(r);                                   // over j2
        #pragma unroll
        for (int k2=0;k2<20;k2++) lin[k2*20+lane]=r[k2]; // X[k1+20*k2]
    }
    __syncwarp();
}

#define WPB 4  // warps (transforms) per block for FFT kernels

// ----------------------------- init: twiddles + zero histogram -----------------------------
__global__ void kInit(float* out){
    int k = threadIdx.x;
    if (k < 400){
        double ang = -2.0*PI_D*(double)k/400.0;
        g_w400[k] = make_float2((float)cos(ang), (float)sin(ang));
    }
    if (k < 11) out[1250+k] = 0.f;
}

// ----------------------------- W1 transpose + row sums -----------------------------
__global__ void kT(const float* __restrict__ W1){
    int idx = blockIdx.x*256 + threadIdx.x;
    if (idx >= 625*512) return;
    int p = idx>>9, hh = idx&511;
    g_W1T[idx] = W1[hh*625+p];
}
__global__ void kR1(){
    int hh = threadIdx.x;
    float s = 0.f;
    for (int p=0;p<625;p++) s += g_W1T[p*512+hh];
    g_R1[hh] = s;
}

// ----------------------------- A0: real input -> row FFT -----------------------------
__global__ void kA0(const float* __restrict__ x){
    __shared__ float2 s_lin[WPB][400];
    __shared__ float2 s_tmp[WPB][421];
    int w = threadIdx.x>>5, lane = threadIdx.x&31;
    int idx = blockIdx.x*WPB + w;
    int b = idx/200, c = idx%200;
    int i = (c<100)? c+100 : c-100;                 // logical row
    const float* xr = x + ((size_t)b*200 + i)*200;
    float2* lin = s_lin[w]; float2* tmp = s_tmp[w];
    for (int m=lane;m<400;m+=32){
        float v = 0.f;
        if (m < 100)      v = xr[m+100];
        else if (m >= 300) v = xr[m-300];
        lin[m] = make_float2(v, 0.f);
    }
    fft400<false>(lin,tmp,lane);
    float2* out = g_S + ((size_t)b*200+c)*400;
    for (int m=lane;m<400;m+=32) out[m]=lin[m];
}

// ----------------------------- B: column FFT * trans * column IFFT -----------------------------
__global__ void kB(const float2* __restrict__ trans){
    __shared__ float2 s_lin[WPB][400];
    __shared__ float2 s_tmp[WPB][421];
    int w = threadIdx.x>>5, lane = threadIdx.x&31;
    int idx = blockIdx.x*WPB + w;
    int b = idx/400, k = idx%400;
    float2* lin = s_lin[w]; float2* tmp = s_tmp[w];
    const float2* Sb = g_S + (size_t)b*200*400;
    for (int r=lane;r<400;r+=32){
        float2 v = make_float2(0.f,0.f);
        if (r < 100)       v = Sb[r*400+k];
        else if (r >= 300) v = Sb[(r-200)*400+k];
        lin[r] = v;
    }
    fft400<false>(lin,tmp,lane);
    for (int r=lane;r<400;r+=32) lin[r] = cmul(lin[r], trans[r*400+k]);
    fft400<true>(lin,tmp,lane);
    float2* S2b = g_S2 + (size_t)b*200*400;
    const float sc = 1.f/400.f;
    for (int c=lane;c<200;c+=32){
        int r = (c<100)? c : c+200;
        float2 v = lin[r];
        S2b[c*400+k] = make_float2(v.x*sc, v.y*sc);
    }
}

// ----------------------------- C: row IFFT + (phasor) + row FFT (fused) -----------------------------
__global__ void kC(const float* __restrict__ ph){   // ph == nullptr for the first diff boundary
    __shared__ float2 s_lin[WPB][400];
    __shared__ float2 s_tmp[WPB][421];
    int w = threadIdx.x>>5, lane = threadIdx.x&31;
    int idx = blockIdx.x*WPB + w;
    int b = idx/200, c = idx%200;
    float2* lin = s_lin[w]; float2* tmp = s_tmp[w];
    const float2* S2b = g_S2 + ((size_t)b*200+c)*400;
    for (int m=lane;m<400;m+=32) lin[m]=S2b[m];
    fft400<true>(lin,tmp,lane);
    int i = (c<100)? c+100 : c-100;                 // logical row
    const float sc = 1.f/400.f;
    float2 keep[7];
    #pragma unroll
    for (int kk=0;kk<7;kk++){
        int cc = lane + kk*32;
        if (cc < 200){
            int rc = (cc<100)? cc : cc+200;
            float2 v = lin[rc];
            v.x *= sc; v.y *= sc;
            if (ph){
                int j = (cc<100)? cc+100 : cc-100;
                float p = ph[i*200+j];
                float sv, cv;
                sincospif(2.f*(sinf(p)+1.f), &sv, &cv); // e^{i*2*pi*(sin(p)+1)}
                v = cmul(v, make_float2(cv, sv));
            }
            keep[kk] = v;
        }
    }
    __syncwarp();
    for (int m=lane;m<400;m+=32) lin[m]=make_float2(0.f,0.f);
    __syncwarp();
    #pragma unroll
    for (int kk=0;kk<7;kk++){
        int cc = lane + kk*32;
        if (cc < 200){
            int rc = (cc<100)? cc : cc+200;
            lin[rc] = keep[kk];
        }
    }
    fft400<false>(lin,tmp,lane);
    float2* out = g_S + ((size_t)b*200+c)*400;
    for (int m=lane;m<400;m+=32) out[m]=lin[m];
}

// ----------------------------- CF: row IFFT -> intensity (logical layout) -----------------------------
__global__ void kCF(){
    __shared__ float2 s_lin[WPB][400];
    __shared__ float2 s_tmp[WPB][421];
    int w = threadIdx.x>>5, lane = threadIdx.x&31;
    int idx = blockIdx.x*WPB + w;
    int b = idx/200, c = idx%200;
    float2* lin = s_lin[w]; float2* tmp = s_tmp[w];
    const float2* S2b = g_S2 + ((size_t)b*200+c)*400;
    for (int m=lane;m<400;m+=32) lin[m]=S2b[m];
    fft400<true>(lin,tmp,lane);
    int i = (c<100)? c+100 : c-100;
    float* Ib = g_I + (size_t)b*40000 + i*200;
    const float sc = 1.f/400.f;
    for (int cc=lane;cc<200;cc+=32){
        int rc = (cc<100)? cc : cc+200;
        int j  = (cc<100)? cc+100 : cc-100;
        float vx = lin[rc].x*sc, vy = lin[rc].y*sc;
        Ib[j] = vx*vx + vy*vy;
    }
}

// ----------------------------- pooling: 8x8 mean -> [p][b] -----------------------------
__global__ void kPool(){
    int idx = blockIdx.x*256 + threadIdx.x;
    if (idx >= 20000) return;
    int b = idx & 31, p = idx >> 5;
    int mi = p/25, mj = p%25;
    const float* base = g_I + (size_t)b*40000 + mi*8*200 + mj*8;
    float s = 0.f;
    #pragma unroll
    for (int u=0;u<8;u++)
        #pragma unroll
        for (int v=0;v<8;v++) s += base[u*200+v];
    g_pool[p*32+b] = s*(1.f/64.f);
}

// ----------------------------- per-window MLP + voting -----------------------------
__global__ void kWin(const float* __restrict__ b1, const float* __restrict__ W2,
                     const float* __restrict__ b2, const float* __restrict__ gamma,
                     const float* __restrict__ beta, float* __restrict__ out)
{
    extern __shared__ float dsm[];
    float* swin = dsm;               // [cell][b] up to 25*32
    float* hid  = dsm + 800;         // [b][hh] 32*512
    float* lg   = dsm + 800 + 16384; // [b][o]  32*10
    __shared__ double red1[256], red2[256];
    __shared__ int   pidx[25];
    __shared__ float s_inv, s_c0;
    __shared__ int   s_a[32];
    __shared__ float s_delta[32];

    int wI = blockIdx.x;
    int i = wI/25, j = wI%25;
    int wr = min(5, 25-i), wc = min(5, 25-j);
    int cells = wr*wc;
    int tid = threadIdx.x;
    if (tid < cells) pidx[tid] = (i + tid/wc)*25 + (j + tid%wc);
    __syncthreads();

    double s1 = 0.0, s2 = 0.0;
    for (int q=tid; q<cells*32; q+=256){
        int cell = q>>5, b = q&31;
        float v = g_pool[pidx[cell]*32 + b];
        swin[q] = v;
        s1 += v; s2 += (double)v*(double)v;
    }
    red1[tid]=s1; red2[tid]=s2;
    __syncthreads();
    for (int st=128; st>0; st>>=1){
        if (tid<st){ red1[tid]+=red1[tid+st]; red2[tid]+=red2[tid+st]; }
        __syncthreads();
    }
    if (tid == 0){
        double mu  = red1[0]/20000.0;
        double var = red2[0]/20000.0 - mu*mu;
        float inv = gamma[0]/(float)sqrt(var + 1e-5);
        s_inv = inv;
        s_c0  = beta[0] - (float)mu*inv;
    }
    __syncthreads();
    float inv = s_inv, c0 = s_c0;

    // hid[b][hh] = relu(c0*R1 + inv*<win,W1win> + b1)
    for (int q=tid; q<32*512; q+=256){
        int b = q>>9, hh = q&511;
        float acc = 0.f;
        for (int cell=0; cell<cells; cell++)
            acc = fmaf(swin[cell*32+b], g_W1T[pidx[cell]*512+hh], acc);
        float pre = fmaf(inv, acc, fmaf(c0, g_R1[hh], b1[hh]));
        hid[b*512+hh] = fmaxf(pre, 0.f);
    }
    __syncthreads();

    for (int t=tid; t<320; t+=256){
        int b = t/10, oo = t%10;
        float acc = b2[oo];
        const float* hb = hid + b*512;
        const float* wv = W2 + oo*512;
        for (int hh=0; hh<512; hh++) acc = fmaf(hb[hh], wv[hh], acc);
        lg[b*10+oo] = acc;
    }
    __syncthreads();

    if (tid < 32){
        int b = tid;
        float lmax = lg[b*10], lmin = lg[b*10];
        int am = 0;
        for (int oo=1;oo<10;oo++){
            float v = lg[b*10+oo];
            if (v > lmax){ lmax = v; am = oo; }
            if (v < lmin)  lmin = v;
        }
        float se = 0.f;
        for (int oo=0;oo<10;oo++) se += expf(lg[b*10+oo]-lmax);
        s_a[b] = am;
        s_delta[b] = (1.f - expf(lmin-lmax))/se;  // pmax - pmin
    }
    __syncthreads();
    if (tid == 0){
        int votes[11];
        for (int k=0;k<11;k++) votes[k]=0;
        for (int b=0;b<32;b++) votes[s_a[b]]++;
        int f0 = 0, best = votes[0];
        for (int k=1;k<11;k++) if (votes[k] > best){ best = votes[k]; f0 = k; }
        float sum = 0.f; int cnt = 0;
        for (int b=0;b<32;b++)
            if (s_a[b]==f0 && s_delta[b]!=0.f){ sum += s_delta[b]; cnt++; }
        int fin;
        if (cnt > 0){ float d1 = sum/(float)cnt; fin = (d1 < 0.2f) ? 0 : f0+1; }
        else fin = f0+1;   // delta1 = NaN; NaN < THR is false
        out[wI]       = (fin==0) ? 0.f : (float)fin;
        out[625+wI]   = (fin!=0) ? 1.f : 0.f;
        atomicAdd(&out[1250+fin], 1.0f);   // exact integer counts -> deterministic
    }
}

// ----------------------------- launch -----------------------------
extern "C" void kernel_launch(void* const* d_in, const int* in_sizes, int n_in,
                              void* d_out, int out_size)
{
    int o = (n_in >= 12 && in_sizes[1] == 1) ? 1 : 0;  // skip batch_size scalar if present
    const float*  x     = (const float*) d_in[0];
    const float2* h     = (const float2*)d_in[1+o];
    const float2* h_pro = (const float2*)d_in[2+o];
    const float2* h_det = (const float2*)d_in[3+o];
    const float*  phase = (const float*) d_in[4+o];
    const float*  W1    = (const float*) d_in[5+o];
    const float*  b1    = (const float*) d_in[6+o];
    const float*  W2    = (const float*) d_in[7+o];
    const float*  b2    = (const float*) d_in[8+o];
    const float*  gamma = (const float*) d_in[9+o];
    const float*  beta  = (const float*) d_in[10+o];
    float* out = (float*)d_out;

    kInit<<<1,512>>>(out);
    kT  <<<1250,256>>>(W1);
    kR1 <<<1,512>>>();

    kA0 <<<1600,128>>>(x);
    kB  <<<3200,128>>>(h_pro);
    kC  <<<1600,128>>>(nullptr);
    for (int l=0; l<4; l++){
        kB <<<3200,128>>>(h);
        kC <<<1600,128>>>(phase + (size_t)l*40000);
    }
    kB  <<<3200,128>>>(h_det);
    kCF <<<1600,128>>>();

    kPool<<<79,256>>>();

    cudaFuncSetAttribute(kWin, cudaFuncAttributeMaxDynamicSharedMemorySize, 70016);
    kWin<<<625,256,70016>>>(b1, W2, b2, gamma, beta, out);
}

// round 3
// speedup vs baseline: 1.3880x; 1.3880x over previous
#include <cuda_runtime.h>
#include <math.h>

#define PI_D 3.14159265358979323846

// ----------------------------- scratch (device globals) -----------------------------
__device__ float2 g_S [32*200*400];   // row-FFT'd field, compact rows, full cols
__device__ float2 g_S2[32*200*400];   // after column FFT * trans * IFFT, compact rows
__device__ float  g_I [32*200*200];   // final intensity, logical layout
__device__ float  g_pool[625*32];     // pooled [p][b]
__device__ float  g_W1T[625*512];     // W1 transposed [p][hh]
__device__ float  g_R1[512];          // row sums of W1
__device__ float2 g_w400[400];        // e^{-2*pi*i*k/400}, fp64-initialized

// ----------------------------- complex helpers -----------------------------
__device__ __forceinline__ float2 cmul(float2 a, float2 b){
    return make_float2(fmaf(a.x,b.x,-a.y*b.y), fmaf(a.x,b.y, a.y*b.x));
}
__device__ __forceinline__ float2 cfma(float2 r, float2 a, float2 w){
    r.x = fmaf(a.x,w.x, fmaf(-a.y,w.y,r.x));
    r.y = fmaf(a.x,w.y, fmaf( a.y,w.x,r.y));
    return r;
}
template<bool INV>
__device__ __forceinline__ float2 TW(int m){   // W400^m (conj if INV)
    float2 v = g_w400[m];
    if (INV) v.y = -v.y;
    return v;
}

// ----------------------------- FFT-20 (registers): n=20, j=5*j1+j2, k=k1+4*k2 ------
// HZ: inputs a[5..14] are identically zero (never read).
template<bool INV, bool HZ>
__device__ __forceinline__ void fft20(float2* a){
    float2 t[20];
    #pragma unroll
    for (int j2=0;j2<5;j2++){
        float2 y0,y1,y2,y3;
        if (HZ){
            float2 x0=a[j2], x3=a[15+j2];
            y0 = make_float2(x0.x+x3.x, x0.y+x3.y);
            y2 = make_float2(x0.x-x3.x, x0.y-x3.y);
            if (!INV){ y1 = make_float2(x0.x - x3.y, x0.y + x3.x);   // x0 + i x3
                       y3 = make_float2(x0.x + x3.y, x0.y - x3.x); } // x0 - i x3
            else     { y1 = make_float2(x0.x + x3.y, x0.y - x3.x);
                       y3 = make_float2(x0.x - x3.y, x0.y + x3.x); }
        } else {
            float2 x0=a[j2], x1=a[5+j2], x2=a[10+j2], x3=a[15+j2];
            float2 s02=make_float2(x0.x+x2.x, x0.y+x2.y);
            float2 d02=make_float2(x0.x-x2.x, x0.y-x2.y);
            float2 s13=make_float2(x1.x+x3.x, x1.y+x3.y);
            float2 d13=make_float2(x1.x-x3.x, x1.y-x3.y);
            y0=make_float2(s02.x+s13.x, s02.y+s13.y);
            y2=make_float2(s02.x-s13.x, s02.y-s13.y);
            if (!INV){ y1=make_float2(d02.x+d13.y, d02.y-d13.x);   // d02 - i*d13
                       y3=make_float2(d02.x-d13.y, d02.y+d13.x); } // d02 + i*d13
            else     { y1=make_float2(d02.x-d13.y, d02.y+d13.x);
                       y3=make_float2(d02.x+d13.y, d02.y-d13.x); }
        }
        t[j2]    = y0;                                   // W20^m = W400^{20m}
        t[5+j2]  = cmul(y1, TW<INV>(20*j2));
        t[10+j2] = cmul(y2, TW<INV>(40*j2));
        t[15+j2] = cmul(y3, TW<INV>(60*j2));
    }
    const float C1f= 0.30901699437494742f, S1f=0.95105651629515357f;
    const float C2f=-0.80901699437494745f, S2f=0.58778525229247313f;
    const float si = INV ? 1.f : -1.f;
    const float2 w1=make_float2(C1f, si*S1f), w2=make_float2(C2f, si*S2f);
    const float2 w3=make_float2(C2f,-si*S2f), w4=make_float2(C1f,-si*S1f);
    #pragma unroll
    for (int k1=0;k1<4;k1++){
        float2 b0=t[k1*5], b1=t[k1*5+1], b2=t[k1*5+2], b3=t[k1*5+3], b4=t[k1*5+4];
        float2 y0=make_float2(b0.x+b1.x+b2.x+b3.x+b4.x, b0.y+b1.y+b2.y+b3.y+b4.y);
        float2 y1=b0; y1=cfma(y1,b1,w1); y1=cfma(y1,b2,w2); y1=cfma(y1,b3,w3); y1=cfma(y1,b4,w4);
        float2 y2=b0; y2=cfma(y2,b1,w2); y2=cfma(y2,b2,w4); y2=cfma(y2,b3,w1); y2=cfma(y2,b4,w3);
        float2 y3=b0; y3=cfma(y3,b1,w3); y3=cfma(y3,b2,w1); y3=cfma(y3,b3,w4); y3=cfma(y3,b4,w2);
        float2 y4=b0; y4=cfma(y4,b1,w4); y4=cfma(y4,b2,w3); y4=cfma(y4,b3,w2); y4=cfma(y4,b4,w1);
        a[k1]=y0; a[k1+4]=y1; a[k1+8]=y2; a[k1+12]=y3; a[k1+16]=y4;
    }
}

// ----------------------------- FFT-400 (warp, 20 active lanes): 20x20 four-step ----
// HZ: lin[100..299] treated as zero (never read).
template<bool INV, bool HZ>
__device__ void fft400(float2* __restrict__ lin, float2* __restrict__ tmp, int lane){
    __syncwarp();
    float2 r[20];
    if (lane < 20){
        if (HZ){
            #pragma unroll
            for (int j1=0;j1<5;j1++)  r[j1]=lin[j1*20+lane];
            #pragma unroll
            for (int j1=15;j1<20;j1++) r[j1]=lin[j1*20+lane];
        } else {
            #pragma unroll
            for (int j1=0;j1<20;j1++) r[j1]=lin[j1*20+lane];
        }
        fft20<INV,HZ>(r);                                // over j1
        #pragma unroll
        for (int k1=1;k1<20;k1++) r[k1]=cmul(r[k1], TW<INV>(lane*k1));  // W400^{j2*k1}
        #pragma unroll
        for (int k1=0;k1<20;k1++) tmp[k1*21+lane]=r[k1];
    }
    __syncwarp();
    if (lane < 20){
        #pragma unroll
        for (int j2=0;j2<20;j2++) r[j2]=tmp[lane*21+j2];
        fft20<INV,false>(r);                             // over j2
        #pragma unroll
        for (int k2=0;k2<20;k2++) lin[k2*20+lane]=r[k2]; // X[k1+20*k2]
    }
    __syncwarp();
}

#define WPB 4  // warps (transforms) per block for row-FFT kernels

// ----------------------------- init: twiddles + zero histogram -----------------------------
__global__ void kInit(float* out){
    int k = threadIdx.x;
    if (k < 400){
        double ang = -2.0*PI_D*(double)k/400.0;
        g_w400[k] = make_float2((float)cos(ang), (float)sin(ang));
    }
    if (k < 11) out[1250+k] = 0.f;
}

// ----------------------------- W1 transpose + row sums -----------------------------
__global__ void kT(const float* __restrict__ W1){
    int idx = blockIdx.x*256 + threadIdx.x;
    if (idx >= 625*512) return;
    int p = idx>>9, hh = idx&511;
    g_W1T[idx] = W1[hh*625+p];
}
__global__ void kR1(const float* __restrict__ W1){
    int hh = threadIdx.x;
    float s = 0.f;
    for (int p=0;p<625;p++) s += W1[hh*625+p];
    g_R1[hh] = s;
}

// ----------------------------- A0: real input -> row FFT -----------------------------
__global__ void kA0(const float* __restrict__ x){
    __shared__ float2 s_lin[WPB][400];
    __shared__ float2 s_tmp[WPB][421];
    int w = threadIdx.x>>5, lane = threadIdx.x&31;
    int idx = blockIdx.x*WPB + w;
    int b = idx/200, c = idx%200;
    int i = (c<100)? c+100 : c-100;                 // logical row
    const float* xr = x + ((size_t)b*200 + i)*200;
    float2* lin = s_lin[w]; float2* tmp = s_tmp[w];
    for (int mm=lane; mm<200; mm+=32){
        int m = (mm<100)? mm : mm+200;
        float v = (mm<100)? xr[mm+100] : xr[mm-100];
        lin[m] = make_float2(v, 0.f);
    }
    fft400<false,true>(lin,tmp,lane);
    float2* out = g_S + ((size_t)b*200+c)*400;
    for (int m=lane;m<400;m+=32) out[m]=lin[m];
}

// ----------------------------- B (tiled): column FFT * trans * column IFFT ---------
// One block: 16 adjacent freq-columns of one batch image. 256 threads (8 warps).
// smem: col[16][401] padded buffers + tmp[8][421] per-warp scratch.
#define KB_SMEM ((16*401 + 8*421)*8)
__global__ void __launch_bounds__(256) kB(const float2* __restrict__ trans){
    extern __shared__ float2 sm[];
    float2* colb = sm;                 // col[kl] -> colb + kl*401
    float2* tmpb = sm + 16*401;        // tmp[w]  -> tmpb + w*421
    int b  = blockIdx.x / 25;
    int k0 = (blockIdx.x % 25) * 16;
    int tid = threadIdx.x;
    const float2* Sb = g_S + (size_t)b*200*400;

    // stage in (coalesced): col[kl][r], r in [0,100) U [300,400)
    for (int idx=tid; idx<200*16; idx+=256){
        int c = idx>>4, kl = idx&15;
        float2 v = Sb[c*400 + k0 + kl];
        int r = (c<100)? c : c+200;
        colb[kl*401 + r] = v;
    }
    __syncthreads();

    // forward column FFTs (half-zero input)
    int w = tid>>5, lane = tid&31;
    fft400<false,true>(colb + w*401,      tmpb + w*421, lane);
    fft400<false,true>(colb + (w+8)*401,  tmpb + w*421, lane);
    __syncthreads();

    // multiply by transfer function (coalesced)
    for (int idx=tid; idx<400*16; idx+=256){
        int r = idx>>4, kl = idx&15;
        colb[kl*401+r] = cmul(colb[kl*401+r], trans[r*400 + k0 + kl]);
    }
    __syncthreads();

    // inverse column FFTs (full)
    fft400<true,false>(colb + w*401,      tmpb + w*421, lane);
    fft400<true,false>(colb + (w+8)*401,  tmpb + w*421, lane);
    __syncthreads();

    // stage out (coalesced), crop rows, scale 1/400
    float2* S2b = g_S2 + (size_t)b*200*400;
    const float sc = 1.f/400.f;
    for (int idx=tid; idx<200*16; idx+=256){
        int c = idx>>4, kl = idx&15;
        int r = (c<100)? c : c+200;
        float2 v = colb[kl*401+r];
        S2b[c*400 + k0 + kl] = make_float2(v.x*sc, v.y*sc);
    }
}

// ----------------------------- C: row IFFT + (phasor) + row FFT (fused) -----------
__global__ void kC(const float* __restrict__ ph){   // ph == nullptr for first boundary
    __shared__ float2 s_lin[WPB][400];
    __shared__ float2 s_tmp[WPB][421];
    int w = threadIdx.x>>5, lane = threadIdx.x&31;
    int idx = blockIdx.x*WPB + w;
    int b = idx/200, c = idx%200;
    float2* lin = s_lin[w]; float2* tmp = s_tmp[w];
    const float2* S2b = g_S2 + ((size_t)b*200+c)*400;
    for (int m=lane;m<400;m+=32) lin[m]=S2b[m];
    fft400<true,false>(lin,tmp,lane);
    int i = (c<100)? c+100 : c-100;                 // logical row
    const float sc = 1.f/400.f;
    float2 keep[7];
    #pragma unroll
    for (int kk=0;kk<7;kk++){
        int cc = lane + kk*32;
        if (cc < 200){
            int rc = (cc<100)? cc : cc+200;
            float2 v = lin[rc];
            v.x *= sc; v.y *= sc;
            if (ph){
                int j = (cc<100)? cc+100 : cc-100;
                float p = ph[i*200+j];
                float sv, cv;
                sincospif(2.f*(sinf(p)+1.f), &sv, &cv); // e^{i*2*pi*(sin(p)+1)}
                v = cmul(v, make_float2(cv, sv));
            }
            keep[kk] = v;
        }
    }
    __syncwarp();
    #pragma unroll
    for (int kk=0;kk<7;kk++){
        int cc = lane + kk*32;
        if (cc < 200){
            int rc = (cc<100)? cc : cc+200;
            lin[rc] = keep[kk];
        }
    }
    fft400<false,true>(lin,tmp,lane);   // half-zero input: middle never read
    float2* out = g_S + ((size_t)b*200+c)*400;
    for (int m=lane;m<400;m+=32) out[m]=lin[m];
}

// ----------------------------- CF: row IFFT -> intensity (logical layout) ----------
__global__ void kCF(){
    __shared__ float2 s_lin[WPB][400];
    __shared__ float2 s_tmp[WPB][421];
    int w = threadIdx.x>>5, lane = threadIdx.x&31;
    int idx = blockIdx.x*WPB + w;
    int b = idx/200, c = idx%200;
    float2* lin = s_lin[w]; float2* tmp = s_tmp[w];
    const float2* S2b = g_S2 + ((size_t)b*200+c)*400;
    for (int m=lane;m<400;m+=32) lin[m]=S2b[m];
    fft400<true,false>(lin,tmp,lane);
    int i = (c<100)? c+100 : c-100;
    float* Ib = g_I + (size_t)b*40000 + i*200;
    const float sc = 1.f/400.f;
    for (int cc=lane;cc<200;cc+=32){
        int rc = (cc<100)? cc : cc+200;
        int j  = (cc<100)? cc+100 : cc-100;
        float vx = lin[rc].x*sc, vy = lin[rc].y*sc;
        Ib[j] = vx*vx + vy*vy;
    }
}

// ----------------------------- pooling: 8x8 mean -> [p][b] -----------------------------
__global__ void kPool(){
    int idx = blockIdx.x*256 + threadIdx.x;
    if (idx >= 20000) return;
    int b = idx & 31, p = idx >> 5;
    int mi = p/25, mj = p%25;
    const float* base = g_I + (size_t)b*40000 + mi*8*200 + mj*8;
    float s = 0.f;
    #pragma unroll
    for (int u=0;u<8;u++)
        #pragma unroll
        for (int v=0;v<8;v++) s += base[u*200+v];
    g_pool[p*32+b] = s*(1.f/64.f);
}

// ----------------------------- per-window MLP + voting -----------------------------
#define HSTR 513    // padded hid stride (bank-conflict-free)
__global__ void __launch_bounds__(256) kWin(
                     const float* __restrict__ b1, const float* __restrict__ W2,
                     const float* __restrict__ b2, const float* __restrict__ gamma,
                     const float* __restrict__ beta, float* __restrict__ out)
{
    extern __shared__ float dsm[];
    float* swin = dsm;                    // [cell][b] up to 25*32
    float* hid  = dsm + 800;              // [b][hh] 32*HSTR
    float* lg   = dsm + 800 + 32*HSTR;    // [b][o]  32*10
    __shared__ double red1[256], red2[256];
    __shared__ int   pidx[25];
    __shared__ float s_inv, s_c0;
    __shared__ int   s_a[32];
    __shared__ float s_delta[32];

    int wI = blockIdx.x;
    int i = wI/25, j = wI%25;
    int wr = min(5, 25-i), wc = min(5, 25-j);
    int cells = wr*wc;
    int tid = threadIdx.x;
    if (tid < cells) pidx[tid] = (i + tid/wc)*25 + (j + tid%wc);
    __syncthreads();

    double s1 = 0.0, s2 = 0.0;
    for (int q=tid; q<cells*32; q+=256){
        int cell = q>>5, b = q&31;
        float v = g_pool[pidx[cell]*32 + b];
        swin[q] = v;
        s1 += v; s2 += (double)v*(double)v;
    }
    red1[tid]=s1; red2[tid]=s2;
    __syncthreads();
    for (int st=128; st>0; st>>=1){
        if (tid<st){ red1[tid]+=red1[tid+st]; red2[tid]+=red2[tid+st]; }
        __syncthreads();
    }
    if (tid == 0){
        double mu  = red1[0]/20000.0;
        double var = red2[0]/20000.0 - mu*mu;
        float inv = gamma[0]/(float)sqrt(var + 1e-5);
        s_inv = inv;
        s_c0  = beta[0] - (float)mu*inv;
    }
    __syncthreads();
    float inv = s_inv, c0 = s_c0;

    // hid[b][hh] = relu(c0*R1 + inv*<win,W1win> + b1); 8 batches per thread,
    // g_W1T loads coalesced over hh and shared across the 8 batches.
    for (int it=0; it<8; it++){
        int task = it*256 + tid;          // 2048 tasks = 4 bgroups x 512 hh
        int hh = task & 511, bg = task >> 9;
        float acc[8];
        #pragma unroll
        for (int u=0;u<8;u++) acc[u]=0.f;
        for (int cell=0; cell<cells; cell++){
            float wv = g_W1T[pidx[cell]*512+hh];
            const float* sw = swin + cell*32 + bg*8;
            #pragma unroll
            for (int u=0;u<8;u++) acc[u] = fmaf(sw[u], wv, acc[u]);
        }
        float base = fmaf(c0, g_R1[hh], b1[hh]);
        #pragma unroll
        for (int u=0;u<8;u++){
            float pre = fmaf(inv, acc[u], base);
            hid[(bg*8+u)*HSTR + hh] = fmaxf(pre, 0.f);
        }
    }
    __syncthreads();

    for (int t=tid; t<320; t+=256){
        int b = t/10, oo = t%10;
        float acc = b2[oo];
        const float* hb = hid + b*HSTR;
        const float* wv = W2 + oo*512;
        for (int hh=0; hh<512; hh++) acc = fmaf(hb[hh], wv[hh], acc);
        lg[b*10+oo] = acc;
    }
    __syncthreads();

    if (tid < 32){
        int b = tid;
        float lmax = lg[b*10], lmin = lg[b*10];
        int am = 0;
        for (int oo=1;oo<10;oo++){
            float v = lg[b*10+oo];
            if (v > lmax){ lmax = v; am = oo; }
            if (v < lmin)  lmin = v;
        }
        float se = 0.f;
        for (int oo=0;oo<10;oo++) se += expf(lg[b*10+oo]-lmax);
        s_a[b] = am;
        s_delta[b] = (1.f - expf(lmin-lmax))/se;  // pmax - pmin
    }
    __syncthreads();
    if (tid == 0){
        int votes[11];
        for (int k=0;k<11;k++) votes[k]=0;
        for (int b=0;b<32;b++) votes[s_a[b]]++;
        int f0 = 0, best = votes[0];
        for (int k=1;k<11;k++) if (votes[k] > best){ best = votes[k]; f0 = k; }
        float sum = 0.f; int cnt = 0;
        for (int b=0;b<32;b++)
            if (s_a[b]==f0 && s_delta[b]!=0.f){ sum += s_delta[b]; cnt++; }
        int fin;
        if (cnt > 0){ float d1 = sum/(float)cnt; fin = (d1 < 0.2f) ? 0 : f0+1; }
        else fin = f0+1;   // delta1 = NaN; NaN < THR is false
        out[wI]       = (fin==0) ? 0.f : (float)fin;
        out[625+wI]   = (fin!=0) ? 1.f : 0.f;
        atomicAdd(&out[1250+fin], 1.0f);   // exact integer counts -> deterministic
    }
}

// ----------------------------- launch -----------------------------
extern "C" void kernel_launch(void* const* d_in, const int* in_sizes, int n_in,
                              void* d_out, int out_size)
{
    int o = (n_in >= 12 && in_sizes[1] == 1) ? 1 : 0;  // skip batch_size scalar if present
    const float*  x     = (const float*) d_in[0];
    const float2* h     = (const float2*)d_in[1+o];
    const float2* h_pro = (const float2*)d_in[2+o];
    const float2* h_det = (const float2*)d_in[3+o];
    const float*  phase = (const float*) d_in[4+o];
    const float*  W1    = (const float*) d_in[5+o];
    const float*  b1    = (const float*) d_in[6+o];
    const float*  W2    = (const float*) d_in[7+o];
    const float*  b2    = (const float*) d_in[8+o];
    const float*  gamma = (const float*) d_in[9+o];
    const float*  beta  = (const float*) d_in[10+o];
    float* out = (float*)d_out;

    static int inited = 0;
    if (!inited){
        cudaFuncSetAttribute(kB,   cudaFuncAttributeMaxDynamicSharedMemorySize, KB_SMEM);
        cudaFuncSetAttribute(kWin, cudaFuncAttributeMaxDynamicSharedMemorySize,
                             (800 + 32*HSTR + 320)*4);
        inited = 1;
    }

    kInit<<<1,512>>>(out);
    kT  <<<1250,256>>>(W1);
    kR1 <<<1,512>>>(W1);

    kA0 <<<1600,128>>>(x);
    kB  <<<800,256,KB_SMEM>>>(h_pro);
    kC  <<<1600,128>>>(nullptr);
    for (int l=0; l<4; l++){
        kB <<<800,256,KB_SMEM>>>(h);
        kC <<<1600,128>>>(phase + (size_t)l*40000);
    }
    kB  <<<800,256,KB_SMEM>>>(h_det);
    kCF <<<1600,128>>>();

    kPool<<<79,256>>>();

    kWin<<<625,256,(800 + 32*HSTR + 320)*4>>>(b1, W2, b2, gamma, beta, out);
}

// round 4
// speedup vs baseline: 1.4690x; 1.0584x over previous
#include <cuda_runtime.h>
#include <math.h>

#define PI_D 3.14159265358979323846

// ----------------------------- scratch (device globals) -----------------------------
__device__ float2 g_S [32*200*400];   // row-FFT'd field, compact rows, full cols
__device__ float2 g_S2[32*200*400];   // after column FFT * trans * IFFT, compact rows
__device__ float2 g_HT[3*400*400];    // transposed transfer functions [m][k][r]
__device__ float  g_I [32*200*200];   // final intensity, logical layout
__device__ float  g_pool[625*32];     // pooled [p][b]
__device__ float  g_W1T[625*512];     // W1 transposed [p][hh]
__device__ float  g_R1[512];          // row sums of W1
__device__ float2 g_w400[400];        // e^{-2*pi*i*k/400}, fp64-initialized

// ----------------------------- complex helpers -----------------------------
__device__ __forceinline__ float2 cmul(float2 a, float2 b){
    return make_float2(fmaf(a.x,b.x,-a.y*b.y), fmaf(a.x,b.y, a.y*b.x));
}
__device__ __forceinline__ float2 cfma(float2 r, float2 a, float2 w){
    r.x = fmaf(a.x,w.x, fmaf(-a.y,w.y,r.x));
    r.y = fmaf(a.x,w.y, fmaf( a.y,w.x,r.y));
    return r;
}
template<bool INV>
__device__ __forceinline__ float2 TW(int m){   // W400^m (conj if INV)
    float2 v = g_w400[m];
    if (INV) v.y = -v.y;
    return v;
}

// ----------------------------- FFT-20 (registers): n=20, j=5*j1+j2, k=k1+4*k2 ------
// HZ:   inputs a[5..14] are identically zero (never read).
// CROP: only outputs k in {0..4, 15..19} are produced (a[5..14] left garbage).
template<bool INV, bool HZ, bool CROP>
__device__ __forceinline__ void fft20(float2* a){
    float2 t[20];
    #pragma unroll
    for (int j2=0;j2<5;j2++){
        float2 y0,y1,y2,y3;
        if (HZ){
            float2 x0=a[j2], x3=a[15+j2];
            y0 = make_float2(x0.x+x3.x, x0.y+x3.y);
            y2 = make_float2(x0.x-x3.x, x0.y-x3.y);
            if (!INV){ y1 = make_float2(x0.x - x3.y, x0.y + x3.x);   // x0 + i x3
                       y3 = make_float2(x0.x + x3.y, x0.y - x3.x); } // x0 - i x3
            else     { y1 = make_float2(x0.x + x3.y, x0.y - x3.x);
                       y3 = make_float2(x0.x - x3.y, x0.y + x3.x); }
        } else {
            float2 x0=a[j2], x1=a[5+j2], x2=a[10+j2], x3=a[15+j2];
            float2 s02=make_float2(x0.x+x2.x, x0.y+x2.y);
            float2 d02=make_float2(x0.x-x2.x, x0.y-x2.y);
            float2 s13=make_float2(x1.x+x3.x, x1.y+x3.y);
            float2 d13=make_float2(x1.x-x3.x, x1.y-x3.y);
            y0=make_float2(s02.x+s13.x, s02.y+s13.y);
            y2=make_float2(s02.x-s13.x, s02.y-s13.y);
            if (!INV){ y1=make_float2(d02.x+d13.y, d02.y-d13.x);   // d02 - i*d13
                       y3=make_float2(d02.x-d13.y, d02.y+d13.x); } // d02 + i*d13
            else     { y1=make_float2(d02.x-d13.y, d02.y+d13.x);
                       y3=make_float2(d02.x+d13.y, d02.y-d13.x); }
        }
        t[j2]    = y0;                                   // W20^m = W400^{20m}
        t[5+j2]  = cmul(y1, TW<INV>(20*j2));
        t[10+j2] = cmul(y2, TW<INV>(40*j2));
        t[15+j2] = cmul(y3, TW<INV>(60*j2));
    }
    const float C1f= 0.30901699437494742f, S1f=0.95105651629515357f;
    const float C2f=-0.80901699437494745f, S2f=0.58778525229247313f;
    const float si = INV ? 1.f : -1.f;
    const float2 w1=make_float2(C1f, si*S1f), w2=make_float2(C2f, si*S2f);
    const float2 w3=make_float2(C2f,-si*S2f), w4=make_float2(C1f,-si*S1f);
    #pragma unroll
    for (int k1=0;k1<4;k1++){
        float2 b0=t[k1*5], b1=t[k1*5+1], b2=t[k1*5+2], b3=t[k1*5+3], b4=t[k1*5+4];
        float2 y0=make_float2(b0.x+b1.x+b2.x+b3.x+b4.x, b0.y+b1.y+b2.y+b3.y+b4.y);
        a[k1]=y0;
        if (!CROP || k1==0){
            float2 y1=b0; y1=cfma(y1,b1,w1); y1=cfma(y1,b2,w2); y1=cfma(y1,b3,w3); y1=cfma(y1,b4,w4);
            a[k1+4]=y1;
        }
        if (!CROP){
            float2 y2=b0; y2=cfma(y2,b1,w2); y2=cfma(y2,b2,w4); y2=cfma(y2,b3,w1); y2=cfma(y2,b4,w3);
            a[k1+8]=y2;
        }
        if (!CROP || k1==3){
            float2 y3=b0; y3=cfma(y3,b1,w3); y3=cfma(y3,b2,w1); y3=cfma(y3,b3,w4); y3=cfma(y3,b4,w2);
            a[k1+12]=y3;
        }
        float2 y4=b0; y4=cfma(y4,b1,w4); y4=cfma(y4,b2,w3); y4=cfma(y4,b3,w2); y4=cfma(y4,b4,w1);
        a[k1+16]=y4;
    }
}

// ----------------------------- FFT-400 (warp, 20 active lanes): 20x20 four-step ----
// HZ: lin[100..299] treated as zero (never read).
// CROP: only outputs lin[0..99], lin[300..399] produced (middle untouched).
template<bool INV, bool HZ, bool CROP>
__device__ void fft400(float2* __restrict__ lin, float2* __restrict__ tmp, int lane){
    __syncwarp();
    float2 r[20];
    if (lane < 20){
        if (HZ){
            #pragma unroll
            for (int j1=0;j1<5;j1++)  r[j1]=lin[j1*20+lane];
            #pragma unroll
            for (int j1=15;j1<20;j1++) r[j1]=lin[j1*20+lane];
        } else {
            #pragma unroll
            for (int j1=0;j1<20;j1++) r[j1]=lin[j1*20+lane];
        }
        fft20<INV,HZ,false>(r);                          // over j1
        #pragma unroll
        for (int k1=1;k1<20;k1++) r[k1]=cmul(r[k1], TW<INV>(lane*k1));  // W400^{j2*k1}
        #pragma unroll
        for (int k1=0;k1<20;k1++) tmp[k1*21+lane]=r[k1];
    }
    __syncwarp();
    if (lane < 20){
        #pragma unroll
        for (int j2=0;j2<20;j2++) r[j2]=tmp[lane*21+j2];
        fft20<INV,false,CROP>(r);                        // over j2
        #pragma unroll
        for (int k2=0;k2<20;k2++)
            if (!CROP || k2<5 || k2>=15) lin[k2*20+lane]=r[k2]; // X[k1+20*k2]
    }
    __syncwarp();
}

#define WPB 4  // warps (transforms) per block for row-FFT kernels

// ----------------------------- init: twiddles + zero histogram -----------------------------
__global__ void kInit(float* out){
    int k = threadIdx.x;
    if (k < 400){
        double ang = -2.0*PI_D*(double)k/400.0;
        g_w400[k] = make_float2((float)cos(ang), (float)sin(ang));
    }
    if (k < 11) out[1250+k] = 0.f;
}

// ----------------------------- transpose transfer functions -----------------------------
__global__ void kHT(const float2* __restrict__ t0, const float2* __restrict__ t1,
                    const float2* __restrict__ t2){
    int idx = blockIdx.x*256 + threadIdx.x;
    if (idx >= 3*160000) return;
    int m = idx / 160000, rem = idx - m*160000;
    int k = rem / 400, r = rem - k*400;
    const float2* src = (m==0)? t0 : (m==1)? t1 : t2;
    g_HT[idx] = src[r*400 + k];
}

// ----------------------------- W1 transpose + row sums -----------------------------
__global__ void kT(const float* __restrict__ W1){
    int idx = blockIdx.x*256 + threadIdx.x;
    if (idx >= 625*512) return;
    int p = idx>>9, hh = idx&511;
    g_W1T[idx] = W1[hh*625+p];
}
__global__ void kR1(const float* __restrict__ W1){
    int hh = threadIdx.x;
    float s = 0.f;
    for (int p=0;p<625;p++) s += W1[hh*625+p];
    g_R1[hh] = s;
}

// ----------------------------- A0: real input -> row FFT -----------------------------
__global__ void kA0(const float* __restrict__ x){
    __shared__ float2 s_lin[WPB][400];
    __shared__ float2 s_tmp[WPB][421];
    int w = threadIdx.x>>5, lane = threadIdx.x&31;
    int idx = blockIdx.x*WPB + w;
    int b = idx/200, c = idx%200;
    int i = (c<100)? c+100 : c-100;                 // logical row
    const float* xr = x + ((size_t)b*200 + i)*200;
    float2* lin = s_lin[w]; float2* tmp = s_tmp[w];
    for (int mm=lane; mm<200; mm+=32){
        int m = (mm<100)? mm : mm+200;
        float v = (mm<100)? xr[mm+100] : xr[mm-100];
        lin[m] = make_float2(v, 0.f);
    }
    fft400<false,true,false>(lin,tmp,lane);
    float2* out = g_S + ((size_t)b*200+c)*400;
    for (int m=lane;m<400;m+=32) out[m]=lin[m];
}

// ----------------------------- B (tiled): column FFT * trans * column IFFT ---------
// One block: 8 adjacent freq-columns of one image, 128 threads (4 warps).
// Static smem: col[8][401] + tmp[4][421]. Each warp runs 2 columns privately.
__global__ void __launch_bounds__(128) kB(int hm){
    __shared__ float2 colb[8][401];
    __shared__ float2 tmpb[4][421];
    int b  = blockIdx.x / 50;
    int k0 = (blockIdx.x % 50) * 8;
    int tid = threadIdx.x;
    const float2* Sb = g_S + (size_t)b*200*400;
    const float2* HT = g_HT + (size_t)hm*160000;

    // stage in (coalesced): col[kl][r], r in [0,100) U [300,400)
    for (int idx=tid; idx<200*8; idx+=128){
        int c = idx>>3, kl = idx&7;
        float2 v = Sb[c*400 + k0 + kl];
        int r = (c<100)? c : c+200;
        colb[kl][r] = v;
    }
    __syncthreads();

    int w = tid>>5, lane = tid&31;
    #pragma unroll
    for (int s=0; s<2; s++){
        int kl = 2*w + s;
        float2* col = colb[kl];
        fft400<false,true,false>(col, tmpb[w], lane);           // fwd, half-zero input
        const float2* ht = HT + (size_t)(k0+kl)*400;
        for (int r=lane; r<400; r+=32) col[r] = cmul(col[r], ht[r]);  // coalesced
        fft400<true,false,true>(col, tmpb[w], lane);            // inv, cropped output
    }
    __syncthreads();

    // stage out (coalesced), crop rows, scale 1/400
    float2* S2b = g_S2 + (size_t)b*200*400;
    const float sc = 1.f/400.f;
    for (int idx=tid; idx<200*8; idx+=128){
        int c = idx>>3, kl = idx&7;
        int r = (c<100)? c : c+200;
        float2 v = colb[kl][r];
        S2b[c*400 + k0 + kl] = make_float2(v.x*sc, v.y*sc);
    }
}

// ----------------------------- C: row IFFT + (phasor) + row FFT (fused) -----------
__global__ void kC(const float* __restrict__ ph){   // ph == nullptr for first boundary
    __shared__ float2 s_lin[WPB][400];
    __shared__ float2 s_tmp[WPB][421];
    int w = threadIdx.x>>5, lane = threadIdx.x&31;
    int idx = blockIdx.x*WPB + w;
    int b = idx/200, c = idx%200;
    float2* lin = s_lin[w]; float2* tmp = s_tmp[w];
    const float2* S2b = g_S2 + ((size_t)b*200+c)*400;
    for (int m=lane;m<400;m+=32) lin[m]=S2b[m];
    fft400<true,false,true>(lin,tmp,lane);          // cropped inverse
    int i = (c<100)? c+100 : c-100;                 // logical row
    const float sc = 1.f/400.f;
    float2 keep[7];
    #pragma unroll
    for (int kk=0;kk<7;kk++){
        int cc = lane + kk*32;
        if (cc < 200){
            int rc = (cc<100)? cc : cc+200;
            float2 v = lin[rc];
            v.x *= sc; v.y *= sc;
            if (ph){
                int j = (cc<100)? cc+100 : cc-100;
                float p = ph[i*200+j];
                float sv, cv;
                sincospif(2.f*(sinf(p)+1.f), &sv, &cv); // e^{i*2*pi*(sin(p)+1)}
                v = cmul(v, make_float2(cv, sv));
            }
            keep[kk] = v;
        }
    }
    __syncwarp();
    #pragma unroll
    for (int kk=0;kk<7;kk++){
        int cc = lane + kk*32;
        if (cc < 200){
            int rc = (cc<100)? cc : cc+200;
            lin[rc] = keep[kk];
        }
    }
    fft400<false,true,false>(lin,tmp,lane);   // half-zero input: middle never read
    float2* out = g_S + ((size_t)b*200+c)*400;
    for (int m=lane;m<400;m+=32) out[m]=lin[m];
}

// ----------------------------- CF: row IFFT -> intensity (logical layout) ----------
__global__ void kCF(){
    __shared__ float2 s_lin[WPB][400];
    __shared__ float2 s_tmp[WPB][421];
    int w = threadIdx.x>>5, lane = threadIdx.x&31;
    int idx = blockIdx.x*WPB + w;
    int b = idx/200, c = idx%200;
    float2* lin = s_lin[w]; float2* tmp = s_tmp[w];
    const float2* S2b = g_S2 + ((size_t)b*200+c)*400;
    for (int m=lane;m<400;m+=32) lin[m]=S2b[m];
    fft400<true,false,true>(lin,tmp,lane);          // cropped inverse
    int i = (c<100)? c+100 : c-100;
    float* Ib = g_I + (size_t)b*40000 + i*200;
    const float sc = 1.f/400.f;
    for (int cc=lane;cc<200;cc+=32){
        int rc = (cc<100)? cc : cc+200;
        int j  = (cc<100)? cc+100 : cc-100;
        float vx = lin[rc].x*sc, vy = lin[rc].y*sc;
        Ib[j] = vx*vx + vy*vy;
    }
}

// ----------------------------- pooling: 8x8 mean -> [p][b] -----------------------------
__global__ void kPool(){
    int idx = blockIdx.x*256 + threadIdx.x;
    if (idx >= 20000) return;
    int b = idx & 31, p = idx >> 5;
    int mi = p/25, mj = p%25;
    const float* base = g_I + (size_t)b*40000 + mi*8*200 + mj*8;
    float s = 0.f;
    #pragma unroll
    for (int u=0;u<8;u++)
        #pragma unroll
        for (int v=0;v<8;v++) s += base[u*200+v];
    g_pool[p*32+b] = s*(1.f/64.f);
}

// ----------------------------- per-window MLP + voting -----------------------------
#define HSTR 513    // padded hid stride (bank-conflict-free)
__global__ void __launch_bounds__(256) kWin(
                     const float* __restrict__ b1, const float* __restrict__ W2,
                     const float* __restrict__ b2, const float* __restrict__ gamma,
                     const float* __restrict__ beta, float* __restrict__ out)
{
    extern __shared__ float dsm[];
    float* swin = dsm;                    // [cell][b] up to 25*32
    float* hid  = dsm + 800;              // [b][hh] 32*HSTR
    float* lg   = dsm + 800 + 32*HSTR;    // [b][o]  32*10
    __shared__ double red1[256], red2[256];
    __shared__ int   pidx[25];
    __shared__ float s_inv, s_c0;
    __shared__ int   s_a[32];
    __shared__ float s_delta[32];

    int wI = blockIdx.x;
    int i = wI/25, j = wI%25;
    int wr = min(5, 25-i), wc = min(5, 25-j);
    int cells = wr*wc;
    int tid = threadIdx.x;
    if (tid < cells) pidx[tid] = (i + tid/wc)*25 + (j + tid%wc);
    __syncthreads();

    double s1 = 0.0, s2 = 0.0;
    for (int q=tid; q<cells*32; q+=256){
        int cell = q>>5, b = q&31;
        float v = g_pool[pidx[cell]*32 + b];
        swin[q] = v;
        s1 += v; s2 += (double)v*(double)v;
    }
    red1[tid]=s1; red2[tid]=s2;
    __syncthreads();
    for (int st=128; st>0; st>>=1){
        if (tid<st){ red1[tid]+=red1[tid+st]; red2[tid]+=red2[tid+st]; }
        __syncthreads();
    }
    if (tid == 0){
        double mu  = red1[0]/20000.0;
        double var = red2[0]/20000.0 - mu*mu;
        float inv = gamma[0]/(float)sqrt(var + 1e-5);
        s_inv = inv;
        s_c0  = beta[0] - (float)mu*inv;
    }
    __syncthreads();
    float inv = s_inv, c0 = s_c0;

    // hid[b][hh] = relu(c0*R1 + inv*<win,W1win> + b1); 8 batches per thread.
    for (int it=0; it<8; it++){
        int task = it*256 + tid;          // 2048 tasks = 4 bgroups x 512 hh
        int hh = task & 511, bg = task >> 9;
        float acc[8];
        #pragma unroll
        for (int u=0;u<8;u++) acc[u]=0.f;
        for (int cell=0; cell<cells; cell++){
            float wv = g_W1T[pidx[cell]*512+hh];
            const float* sw = swin + cell*32 + bg*8;
            #pragma unroll
            for (int u=0;u<8;u++) acc[u] = fmaf(sw[u], wv, acc[u]);
        }
        float base = fmaf(c0, g_R1[hh], b1[hh]);
        #pragma unroll
        for (int u=0;u<8;u++){
            float pre = fmaf(inv, acc[u], base);
            hid[(bg*8+u)*HSTR + hh] = fmaxf(pre, 0.f);
        }
    }
    __syncthreads();

    for (int t=tid; t<320; t+=256){
        int b = t/10, oo = t%10;
        float acc = b2[oo];
        const float* hb = hid + b*HSTR;
        const float* wv = W2 + oo*512;
        for (int hh=0; hh<512; hh++) acc = fmaf(hb[hh], wv[hh], acc);
        lg[b*10+oo] = acc;
    }
    __syncthreads();

    if (tid < 32){
        int b = tid;
        float lmax = lg[b*10], lmin = lg[b*10];
        int am = 0;
        for (int oo=1;oo<10;oo++){
            float v = lg[b*10+oo];
            if (v > lmax){ lmax = v; am = oo; }
            if (v < lmin)  lmin = v;
        }
        float se = 0.f;
        for (int oo=0;oo<10;oo++) se += expf(lg[b*10+oo]-lmax);
        s_a[b] = am;
        s_delta[b] = (1.f - expf(lmin-lmax))/se;  // pmax - pmin
    }
    __syncthreads();
    if (tid == 0){
        int votes[11];
        for (int k=0;k<11;k++) votes[k]=0;
        for (int b=0;b<32;b++) votes[s_a[b]]++;
        int f0 = 0, best = votes[0];
        for (int k=1;k<11;k++) if (votes[k] > best){ best = votes[k]; f0 = k; }
        float sum = 0.f; int cnt = 0;
        for (int b=0;b<32;b++)
            if (s_a[b]==f0 && s_delta[b]!=0.f){ sum += s_delta[b]; cnt++; }
        int fin;
        if (cnt > 0){ float d1 = sum/(float)cnt; fin = (d1 < 0.2f) ? 0 : f0+1; }
        else fin = f0+1;   // delta1 = NaN; NaN < THR is false
        out[wI]       = (fin==0) ? 0.f : (float)fin;
        out[625+wI]   = (fin!=0) ? 1.f : 0.f;
        atomicAdd(&out[1250+fin], 1.0f);   // exact integer counts -> deterministic
    }
}

// ----------------------------- launch -----------------------------
extern "C" void kernel_launch(void* const* d_in, const int* in_sizes, int n_in,
                              void* d_out, int out_size)
{
    int o = (n_in >= 12 && in_sizes[1] == 1) ? 1 : 0;  // skip batch_size scalar if present
    const float*  x     = (const float*) d_in[0];
    const float2* h     = (const float2*)d_in[1+o];
    const float2* h_pro = (const float2*)d_in[2+o];
    const float2* h_det = (const float2*)d_in[3+o];
    const float*  phase = (const float*) d_in[4+o];
    const float*  W1    = (const float*) d_in[5+o];
    const float*  b1    = (const float*) d_in[6+o];
    const float*  W2    = (const float*) d_in[7+o];
    const float*  b2    = (const float*) d_in[8+o];
    const float*  gamma = (const float*) d_in[9+o];
    const float*  beta  = (const float*) d_in[10+o];
    float* out = (float*)d_out;

    cudaFuncSetAttribute(kWin, cudaFuncAttributeMaxDynamicSharedMemorySize,
                         (800 + 32*HSTR + 320)*4);

    kInit<<<1,512>>>(out);
    kHT <<<1875,256>>>(h_pro, h, h_det);   // [0]=h_pro, [1]=h, [2]=h_det
    kT  <<<1250,256>>>(W1);
    kR1 <<<1,512>>>(W1);

    kA0 <<<1600,128>>>(x);
    kB  <<<1600,128>>>(0);                 // h_pro
    kC  <<<1600,128>>>(nullptr);
    for (int l=0; l<4; l++){
        kB <<<1600,128>>>(1);              // h (transposed once, reused 4x)
        kC <<<1600,128>>>(phase + (size_t)l*40000);
    }
    kB  <<<1600,128>>>(2);                 // h_det
    kCF <<<1600,128>>>();

    kPool<<<79,256>>>();

    kWin<<<625,256,(800 + 32*HSTR + 320)*4>>>(b1, W2, b2, gamma, beta, out);
}

// round 5
// speedup vs baseline: 1.5084x; 1.0268x over previous
#include <cuda_runtime.h>
#include <math.h>

#define PI_D 3.14159265358979323846

// ----------------------------- scratch (device globals) -----------------------------
__device__ float2 g_S [32*200*400];   // row-FFT'd field, compact rows, full cols
__device__ float2 g_S2[32*200*400];   // after column FFT * trans * IFFT, compact rows
__device__ float2 g_HT[3*400*400];    // transposed transfer functions [m][k][r]
__device__ float  g_I [32*200*200];   // final intensity, logical layout
__device__ float  g_pool[625*32];     // pooled [p][b]
__device__ float  g_W1T[625*512];     // W1 transposed [p][hh]
__device__ float  g_R1[512];          // row sums of W1
__device__ float2 g_w400[400];        // e^{-2*pi*i*k/400}, fp64-initialized

// ----------------------------- complex helpers -----------------------------
__device__ __forceinline__ float2 cmul(float2 a, float2 b){
    return make_float2(fmaf(a.x,b.x,-a.y*b.y), fmaf(a.x,b.y, a.y*b.x));
}
__device__ __forceinline__ float2 cfma(float2 r, float2 a, float2 w){
    r.x = fmaf(a.x,w.x, fmaf(-a.y,w.y,r.x));
    r.y = fmaf(a.x,w.y, fmaf( a.y,w.x,r.y));
    return r;
}
template<bool INV>
__device__ __forceinline__ float2 TW(int m){   // W400^m (conj if INV)
    float2 v = g_w400[m];
    if (INV) v.y = -v.y;
    return v;
}

// ----------------------------- FFT-20 (registers): n=20, j=5*j1+j2, k=k1+4*k2 ------
// HZ:   inputs a[5..14] are identically zero (never read).
// CROP: only outputs k in {0..4, 15..19} are produced (a[5..14] left garbage).
template<bool INV, bool HZ, bool CROP>
__device__ __forceinline__ void fft20(float2* a){
    float2 t[20];
    #pragma unroll
    for (int j2=0;j2<5;j2++){
        float2 y0,y1,y2,y3;
        if (HZ){
            float2 x0=a[j2], x3=a[15+j2];
            y0 = make_float2(x0.x+x3.x, x0.y+x3.y);
            y2 = make_float2(x0.x-x3.x, x0.y-x3.y);
            if (!INV){ y1 = make_float2(x0.x - x3.y, x0.y + x3.x);   // x0 + i x3
                       y3 = make_float2(x0.x + x3.y, x0.y - x3.x); } // x0 - i x3
            else     { y1 = make_float2(x0.x + x3.y, x0.y - x3.x);
                       y3 = make_float2(x0.x - x3.y, x0.y + x3.x); }
        } else {
            float2 x0=a[j2], x1=a[5+j2], x2=a[10+j2], x3=a[15+j2];
            float2 s02=make_float2(x0.x+x2.x, x0.y+x2.y);
            float2 d02=make_float2(x0.x-x2.x, x0.y-x2.y);
            float2 s13=make_float2(x1.x+x3.x, x1.y+x3.y);
            float2 d13=make_float2(x1.x-x3.x, x1.y-x3.y);
            y0=make_float2(s02.x+s13.x, s02.y+s13.y);
            y2=make_float2(s02.x-s13.x, s02.y-s13.y);
            if (!INV){ y1=make_float2(d02.x+d13.y, d02.y-d13.x);   // d02 - i*d13
                       y3=make_float2(d02.x-d13.y, d02.y+d13.x); } // d02 + i*d13
            else     { y1=make_float2(d02.x-d13.y, d02.y+d13.x);
                       y3=make_float2(d02.x+d13.y, d02.y-d13.x); }
        }
        t[j2]    = y0;                                   // W20^m = W400^{20m}
        t[5+j2]  = cmul(y1, TW<INV>(20*j2));
        t[10+j2] = cmul(y2, TW<INV>(40*j2));
        t[15+j2] = cmul(y3, TW<INV>(60*j2));
    }
    const float C1f= 0.30901699437494742f, S1f=0.95105651629515357f;
    const float C2f=-0.80901699437494745f, S2f=0.58778525229247313f;
    const float si = INV ? 1.f : -1.f;
    const float2 w1=make_float2(C1f, si*S1f), w2=make_float2(C2f, si*S2f);
    const float2 w3=make_float2(C2f,-si*S2f), w4=make_float2(C1f,-si*S1f);
    #pragma unroll
    for (int k1=0;k1<4;k1++){
        float2 b0=t[k1*5], b1=t[k1*5+1], b2=t[k1*5+2], b3=t[k1*5+3], b4=t[k1*5+4];
        float2 y0=make_float2(b0.x+b1.x+b2.x+b3.x+b4.x, b0.y+b1.y+b2.y+b3.y+b4.y);
        a[k1]=y0;
        if (!CROP || k1==0){
            float2 y1=b0; y1=cfma(y1,b1,w1); y1=cfma(y1,b2,w2); y1=cfma(y1,b3,w3); y1=cfma(y1,b4,w4);
            a[k1+4]=y1;
        }
        if (!CROP){
            float2 y2=b0; y2=cfma(y2,b1,w2); y2=cfma(y2,b2,w4); y2=cfma(y2,b3,w1); y2=cfma(y2,b4,w3);
            a[k1+8]=y2;
        }
        if (!CROP || k1==3){
            float2 y3=b0; y3=cfma(y3,b1,w3); y3=cfma(y3,b2,w1); y3=cfma(y3,b3,w4); y3=cfma(y3,b4,w2);
            a[k1+12]=y3;
        }
        float2 y4=b0; y4=cfma(y4,b1,w4); y4=cfma(y4,b2,w3); y4=cfma(y4,b3,w2); y4=cfma(y4,b4,w1);
        a[k1+16]=y4;
    }
}

// ----------------------------- FFT-400 (warp, 20 active lanes): 20x20 four-step ----
// (kept for row kernels kA0/kC/kCF)
template<bool INV, bool HZ, bool CROP>
__device__ void fft400(float2* __restrict__ lin, float2* __restrict__ tmp, int lane){
    __syncwarp();
    float2 r[20];
    if (lane < 20){
        if (HZ){
            #pragma unroll
            for (int j1=0;j1<5;j1++)  r[j1]=lin[j1*20+lane];
            #pragma unroll
            for (int j1=15;j1<20;j1++) r[j1]=lin[j1*20+lane];
        } else {
            #pragma unroll
            for (int j1=0;j1<20;j1++) r[j1]=lin[j1*20+lane];
        }
        fft20<INV,HZ,false>(r);                          // over j1
        #pragma unroll
        for (int k1=1;k1<20;k1++) r[k1]=cmul(r[k1], TW<INV>(lane*k1));  // W400^{j2*k1}
        #pragma unroll
        for (int k1=0;k1<20;k1++) tmp[k1*21+lane]=r[k1];
    }
    __syncwarp();
    if (lane < 20){
        #pragma unroll
        for (int j2=0;j2<20;j2++) r[j2]=tmp[lane*21+j2];
        fft20<INV,false,CROP>(r);                        // over j2
        #pragma unroll
        for (int k2=0;k2<20;k2++)
            if (!CROP || k2<5 || k2>=15) lin[k2*20+lane]=r[k2]; // X[k1+20*k2]
    }
    __syncwarp();
}

#define WPB 4  // warps (transforms) per block for row-FFT kernels

// ----------------------------- init: twiddles + zero histogram -----------------------------
__global__ void kInit(float* out){
    int k = threadIdx.x;
    if (k < 400){
        double ang = -2.0*PI_D*(double)k/400.0;
        g_w400[k] = make_float2((float)cos(ang), (float)sin(ang));
    }
    if (k < 11) out[1250+k] = 0.f;
}

// ----------------------------- transpose transfer functions (tiled) -----------------------------
__global__ void kHT(const float2* __restrict__ t0, const float2* __restrict__ t1,
                    const float2* __restrict__ t2){
    __shared__ float2 tile[32][33];
    int m = blockIdx.z;
    const float2* src = (m==0)? t0 : (m==1)? t1 : t2;
    int r0 = blockIdx.y*32, k0 = blockIdx.x*32;
    int tx = threadIdx.x, ty = threadIdx.y;   // 32 x 8
    for (int yy=ty; yy<32; yy+=8){
        int r = r0+yy, k = k0+tx;
        if (r<400 && k<400) tile[yy][tx] = src[r*400+k];
    }
    __syncthreads();
    for (int yy=ty; yy<32; yy+=8){
        int k = k0+yy, r = r0+tx;
        if (r<400 && k<400) g_HT[(size_t)m*160000 + k*400 + r] = tile[tx][yy];
    }
}

// ----------------------------- W1 transpose + row sums -----------------------------
__global__ void kT(const float* __restrict__ W1){
    int idx = blockIdx.x*256 + threadIdx.x;
    if (idx >= 625*512) return;
    int p = idx>>9, hh = idx&511;
    g_W1T[idx] = W1[hh*625+p];
}
__global__ void kR1(const float* __restrict__ W1){   // grid 512, block 128
    __shared__ float red[128];
    int hh = blockIdx.x, tid = threadIdx.x;
    float s = 0.f;
    for (int p=tid; p<625; p+=128) s += W1[hh*625+p];
    red[tid] = s;
    __syncthreads();
    for (int st=64; st>0; st>>=1){
        if (tid<st) red[tid]+=red[tid+st];
        __syncthreads();
    }
    if (tid==0) g_R1[hh] = red[0];
}

// ----------------------------- A0: real input -> row FFT -----------------------------
__global__ void kA0(const float* __restrict__ x){
    __shared__ float2 s_lin[WPB][400];
    __shared__ float2 s_tmp[WPB][421];
    int w = threadIdx.x>>5, lane = threadIdx.x&31;
    int idx = blockIdx.x*WPB + w;
    int b = idx/200, c = idx%200;
    int i = (c<100)? c+100 : c-100;                 // logical row
    const float* xr = x + ((size_t)b*200 + i)*200;
    float2* lin = s_lin[w]; float2* tmp = s_tmp[w];
    for (int mm=lane; mm<200; mm+=32){
        int m = (mm<100)? mm : mm+200;
        float v = (mm<100)? xr[mm+100] : xr[mm-100];
        lin[m] = make_float2(v, 0.f);
    }
    fft400<false,true,false>(lin,tmp,lane);
    float2* out = g_S + ((size_t)b*200+c)*400;
    for (int m=lane;m<400;m+=32) out[m]=lin[m];
}

// ----------------------------- B2 (task-parallel): col FFT * trans * col IFFT ------
// One block: 8 freq-columns, 160 threads; each thread owns ONE fft20 per stage.
// smem: colA[8][403] data (natural order) + colT[8][421] stage intermediate.
#define KB2_SMEM ((8*403 + 8*421)*8)
__global__ void __launch_bounds__(160) kB2(int hm){
    extern __shared__ float2 sm[];
    float2* colA = sm;              // col kl at colA + kl*403
    float2* colT = sm + 8*403;      // col kl at colT + kl*421
    int b  = blockIdx.x / 50;
    int k0 = (blockIdx.x % 50) * 8;
    int tid = threadIdx.x;
    const float2* Sb = g_S + (size_t)b*200*400;
    const float2* HT = g_HT + (size_t)hm*160000 + (size_t)k0*400;

    // stage in (coalesced): corners only (forward input is half-zero)
    for (int idx=tid; idx<1600; idx+=160){
        int c = idx>>3, kl = idx&7;
        float2 v = Sb[c*400 + k0 + kl];
        int r = (c<100)? c : c+200;
        colA[kl*403 + r] = v;
    }
    __syncthreads();

    int kl = tid/20, jq = tid%20;
    float2* A  = colA + kl*403;
    float2* Tm = colT + kl*421;

    { // fwd stage1 over j1 (HZ), jq = j2
        float2 r[20];
        #pragma unroll
        for (int j1=0;j1<5;j1++)   r[j1]=A[j1*20+jq];
        #pragma unroll
        for (int j1=15;j1<20;j1++) r[j1]=A[j1*20+jq];
        fft20<false,true,false>(r);
        #pragma unroll
        for (int k1=1;k1<20;k1++) r[k1]=cmul(r[k1], TW<false>(jq*k1));
        #pragma unroll
        for (int k1=0;k1<20;k1++) Tm[k1*21+jq]=r[k1];
    }
    __syncthreads();
    { // fwd stage2 over j2, jq = k1 -> natural order X[k1+20*k2]
        float2 r[20];
        #pragma unroll
        for (int j2=0;j2<20;j2++) r[j2]=Tm[jq*21+j2];
        fft20<false,false,false>(r);
        #pragma unroll
        for (int k2=0;k2<20;k2++) A[k2*20+jq]=r[k2];
    }
    __syncthreads();
    // multiply by transfer function (smem + global both coalesced)
    for (int i=tid; i<3200; i+=160){
        int c2 = i/400, m = i - c2*400;
        colA[c2*403+m] = cmul(colA[c2*403+m], HT[c2*400+m]);
    }
    __syncthreads();
    { // inv stage1 over j1 (full input), jq = j2
        float2 r[20];
        #pragma unroll
        for (int j1=0;j1<20;j1++) r[j1]=A[j1*20+jq];
        fft20<true,false,false>(r);
        #pragma unroll
        for (int k1=1;k1<20;k1++) r[k1]=cmul(r[k1], TW<true>(jq*k1));
        #pragma unroll
        for (int k1=0;k1<20;k1++) Tm[k1*21+jq]=r[k1];
    }
    __syncthreads();
    { // inv stage2 over j2 (cropped outputs), jq = k1
        float2 r[20];
        #pragma unroll
        for (int j2=0;j2<20;j2++) r[j2]=Tm[jq*21+j2];
        fft20<true,false,true>(r);
        #pragma unroll
        for (int k2=0;k2<20;k2++)
            if (k2<5 || k2>=15) A[k2*20+jq]=r[k2];
    }
    __syncthreads();

    // stage out (coalesced), crop rows, scale 1/400
    float2* S2b = g_S2 + (size_t)b*200*400;
    const float sc = 1.f/400.f;
    for (int idx=tid; idx<1600; idx+=160){
        int c = idx>>3, klx = idx&7;
        int r = (c<100)? c : c+200;
        float2 v = colA[klx*403 + r];
        S2b[c*400 + k0 + klx] = make_float2(v.x*sc, v.y*sc);
    }
}

// ----------------------------- C: row IFFT + (phasor) + row FFT (fused) -----------
__global__ void kC(const float* __restrict__ ph){   // ph == nullptr for first boundary
    __shared__ float2 s_lin[WPB][400];
    __shared__ float2 s_tmp[WPB][421];
    int w = threadIdx.x>>5, lane = threadIdx.x&31;
    int idx = blockIdx.x*WPB + w;
    int b = idx/200, c = idx%200;
    float2* lin = s_lin[w]; float2* tmp = s_tmp[w];
    const float2* S2b = g_S2 + ((size_t)b*200+c)*400;
    for (int m=lane;m<400;m+=32) lin[m]=S2b[m];
    fft400<true,false,true>(lin,tmp,lane);          // cropped inverse
    int i = (c<100)? c+100 : c-100;                 // logical row
    const float sc = 1.f/400.f;
    float2 keep[7];
    #pragma unroll
    for (int kk=0;kk<7;kk++){
        int cc = lane + kk*32;
        if (cc < 200){
            int rc = (cc<100)? cc : cc+200;
            float2 v = lin[rc];
            v.x *= sc; v.y *= sc;
            if (ph){
                int j = (cc<100)? cc+100 : cc-100;
                float p = ph[i*200+j];
                float sv, cv;
                sincospif(2.f*(sinf(p)+1.f), &sv, &cv); // e^{i*2*pi*(sin(p)+1)}
                v = cmul(v, make_float2(cv, sv));
            }
            keep[kk] = v;
        }
    }
    __syncwarp();
    #pragma unroll
    for (int kk=0;kk<7;kk++){
        int cc = lane + kk*32;
        if (cc < 200){
            int rc = (cc<100)? cc : cc+200;
            lin[rc] = keep[kk];
        }
    }
    fft400<false,true,false>(lin,tmp,lane);   // half-zero input: middle never read
    float2* out = g_S + ((size_t)b*200+c)*400;
    for (int m=lane;m<400;m+=32) out[m]=lin[m];
}

// ----------------------------- CF: row IFFT -> intensity (logical layout) ----------
__global__ void kCF(){
    __shared__ float2 s_lin[WPB][400];
    __shared__ float2 s_tmp[WPB][421];
    int w = threadIdx.x>>5, lane = threadIdx.x&31;
    int idx = blockIdx.x*WPB + w;
    int b = idx/200, c = idx%200;
    float2* lin = s_lin[w]; float2* tmp = s_tmp[w];
    const float2* S2b = g_S2 + ((size_t)b*200+c)*400;
    for (int m=lane;m<400;m+=32) lin[m]=S2b[m];
    fft400<true,false,true>(lin,tmp,lane);          // cropped inverse
    int i = (c<100)? c+100 : c-100;
    float* Ib = g_I + (size_t)b*40000 + i*200;
    const float sc = 1.f/400.f;
    for (int cc=lane;cc<200;cc+=32){
        int rc = (cc<100)? cc : cc+200;
        int j  = (cc<100)? cc+100 : cc-100;
        float vx = lin[rc].x*sc, vy = lin[rc].y*sc;
        Ib[j] = vx*vx + vy*vy;
    }
}

// ----------------------------- pooling: 8x8 mean -> [p][b] -----------------------------
__global__ void kPool(){
    int idx = blockIdx.x*256 + threadIdx.x;
    if (idx >= 20000) return;
    int b = idx & 31, p = idx >> 5;
    int mi = p/25, mj = p%25;
    const float* base = g_I + (size_t)b*40000 + mi*8*200 + mj*8;
    float s = 0.f;
    #pragma unroll
    for (int u=0;u<8;u++)
        #pragma unroll
        for (int v=0;v<8;v++) s += base[u*200+v];
    g_pool[p*32+b] = s*(1.f/64.f);
}

// ----------------------------- per-window MLP + voting -----------------------------
#define HSTR 513    // padded hid stride (bank-conflict-free)
__global__ void __launch_bounds__(256) kWin(
                     const float* __restrict__ b1, const float* __restrict__ W2,
                     const float* __restrict__ b2, const float* __restrict__ gamma,
                     const float* __restrict__ beta, float* __restrict__ out)
{
    extern __shared__ float dsm[];
    float* swin = dsm;                    // [cell][b] up to 25*32
    float* hid  = dsm + 800;              // [b][hh] 32*HSTR
    float* lg   = dsm + 800 + 32*HSTR;    // [b][o]  32*10
    __shared__ double red1[256], red2[256];
    __shared__ int   pidx[25];
    __shared__ float s_inv, s_c0;
    __shared__ int   s_a[32];
    __shared__ float s_delta[32];

    int wI = blockIdx.x;
    int i = wI/25, j = wI%25;
    int wr = min(5, 25-i), wc = min(5, 25-j);
    int cells = wr*wc;
    int tid = threadIdx.x;
    if (tid < cells) pidx[tid] = (i + tid/wc)*25 + (j + tid%wc);
    __syncthreads();

    double s1 = 0.0, s2 = 0.0;
    for (int q=tid; q<cells*32; q+=256){
        int cell = q>>5, b = q&31;
        float v = g_pool[pidx[cell]*32 + b];
        swin[q] = v;
        s1 += v; s2 += (double)v*(double)v;
    }
    red1[tid]=s1; red2[tid]=s2;
    __syncthreads();
    for (int st=128; st>0; st>>=1){
        if (tid<st){ red1[tid]+=red1[tid+st]; red2[tid]+=red2[tid+st]; }
        __syncthreads();
    }
    if (tid == 0){
        double mu  = red1[0]/20000.0;
        double var = red2[0]/20000.0 - mu*mu;
        float inv = gamma[0]/(float)sqrt(var + 1e-5);
        s_inv = inv;
        s_c0  = beta[0] - (float)mu*inv;
    }
    __syncthreads();
    float inv = s_inv, c0 = s_c0;

    // hid[b][hh] = relu(c0*R1 + inv*<win,W1win> + b1); 8 batches per thread.
    for (int it=0; it<8; it++){
        int task = it*256 + tid;          // 2048 tasks = 4 bgroups x 512 hh
        int hh = task & 511, bg = task >> 9;
        float acc[8];
        #pragma unroll
        for (int u=0;u<8;u++) acc[u]=0.f;
        for (int cell=0; cell<cells; cell++){
            float wv = g_W1T[pidx[cell]*512+hh];
            const float* sw = swin + cell*32 + bg*8;
            #pragma unroll
            for (int u=0;u<8;u++) acc[u] = fmaf(sw[u], wv, acc[u]);
        }
        float base = fmaf(c0, g_R1[hh], b1[hh]);
        #pragma unroll
        for (int u=0;u<8;u++){
            float pre = fmaf(inv, acc[u], base);
            hid[(bg*8+u)*HSTR + hh] = fmaxf(pre, 0.f);
        }
    }
    __syncthreads();

    for (int t=tid; t<320; t+=256){
        int b = t/10, oo = t%10;
        float acc = b2[oo];
        const float* hb = hid + b*HSTR;
        const float* wv = W2 + oo*512;
        for (int hh=0; hh<512; hh++) acc = fmaf(hb[hh], wv[hh], acc);
        lg[b*10+oo] = acc;
    }
    __syncthreads();

    if (tid < 32){
        int b = tid;
        float lmax = lg[b*10], lmin = lg[b*10];
        int am = 0;
        for (int oo=1;oo<10;oo++){
            float v = lg[b*10+oo];
            if (v > lmax){ lmax = v; am = oo; }
            if (v < lmin)  lmin = v;
        }
        float se = 0.f;
        for (int oo=0;oo<10;oo++) se += expf(lg[b*10+oo]-lmax);
        s_a[b] = am;
        s_delta[b] = (1.f - expf(lmin-lmax))/se;  // pmax - pmin
    }
    __syncthreads();
    if (tid == 0){
        int votes[11];
        for (int k=0;k<11;k++) votes[k]=0;
        for (int b=0;b<32;b++) votes[s_a[b]]++;
        int f0 = 0, best = votes[0];
        for (int k=1;k<11;k++) if (votes[k] > best){ best = votes[k]; f0 = k; }
        float sum = 0.f; int cnt = 0;
        for (int b=0;b<32;b++)
            if (s_a[b]==f0 && s_delta[b]!=0.f){ sum += s_delta[b]; cnt++; }
        int fin;
        if (cnt > 0){ float d1 = sum/(float)cnt; fin = (d1 < 0.2f) ? 0 : f0+1; }
        else fin = f0+1;   // delta1 = NaN; NaN < THR is false
        out[wI]       = (fin==0) ? 0.f : (float)fin;
        out[625+wI]   = (fin!=0) ? 1.f : 0.f;
        atomicAdd(&out[1250+fin], 1.0f);   // exact integer counts -> deterministic
    }
}

// ----------------------------- launch -----------------------------
extern "C" void kernel_launch(void* const* d_in, const int* in_sizes, int n_in,
                              void* d_out, int out_size)
{
    int o = (n_in >= 12 && in_sizes[1] == 1) ? 1 : 0;  // skip batch_size scalar if present
    const float*  x     = (const float*) d_in[0];
    const float2* h     = (const float2*)d_in[1+o];
    const float2* h_pro = (const float2*)d_in[2+o];
    const float2* h_det = (const float2*)d_in[3+o];
    const float*  phase = (const float*) d_in[4+o];
    const float*  W1    = (const float*) d_in[5+o];
    const float*  b1    = (const float*) d_in[6+o];
    const float*  W2    = (const float*) d_in[7+o];
    const float*  b2    = (const float*) d_in[8+o];
    const float*  gamma = (const float*) d_in[9+o];
    const float*  beta  = (const float*) d_in[10+o];
    float* out = (float*)d_out;

    cudaFuncSetAttribute(kWin, cudaFuncAttributeMaxDynamicSharedMemorySize,
                         (800 + 32*HSTR + 320)*4);
    cudaFuncSetAttribute(kB2, cudaFuncAttributeMaxDynamicSharedMemorySize, KB2_SMEM);

    kInit<<<1,512>>>(out);
    kHT <<<dim3(13,13,3),dim3(32,8)>>>(h_pro, h, h_det);   // [0]=h_pro, [1]=h, [2]=h_det
    kT  <<<1250,256>>>(W1);
    kR1 <<<512,128>>>(W1);

    kA0 <<<1600,128>>>(x);
    kB2 <<<1600,160,KB2_SMEM>>>(0);        // h_pro
    kC  <<<1600,128>>>(nullptr);
    for (int l=0; l<4; l++){
        kB2 <<<1600,160,KB2_SMEM>>>(1);    // h (transposed once, reused 4x)
        kC  <<<1600,128>>>(phase + (size_t)l*40000);
    }
    kB2 <<<1600,160,KB2_SMEM>>>(2);        // h_det
    kCF <<<1600,128>>>();

    kPool<<<79,256>>>();

    kWin<<<625,256,(800 + 32*HSTR + 320)*4>>>(b1, W2, b2, gamma, beta, out);
}

// round 6
// speedup vs baseline: 1.7196x; 1.1400x over previous
#include <cuda_runtime.h>
#include <math.h>

#define PI_D 3.14159265358979323846

// ----------------------------- scratch (device globals) -----------------------------
__device__ float2 g_S [32*200*400];   // row-FFT'd field, compact rows, full cols
__device__ float2 g_S2[32*200*400];   // after column FFT * trans * IFFT, compact rows
__device__ float2 g_HT[3*400*400];    // transposed transfer functions [m][k][r]
__device__ float  g_I [32*200*200];   // final intensity, logical layout
__device__ float  g_pool[625*32];     // pooled [p][b]
__device__ float  g_W1T[625*512];     // W1 transposed [p][hh]
__device__ float  g_R1[512];          // row sums of W1
__device__ float2 g_w400[400];        // e^{-2*pi*i*k/400}, fp64-initialized

// ----------------------------- complex helpers -----------------------------
__device__ __forceinline__ float2 cmul(float2 a, float2 b){
    return make_float2(fmaf(a.x,b.x,-a.y*b.y), fmaf(a.x,b.y, a.y*b.x));
}
__device__ __forceinline__ float2 cfma(float2 r, float2 a, float2 w){
    r.x = fmaf(a.x,w.x, fmaf(-a.y,w.y,r.x));
    r.y = fmaf(a.x,w.y, fmaf( a.y,w.x,r.y));
    return r;
}
template<bool INV>
__device__ __forceinline__ float2 TW(int m){   // W400^m (conj if INV)
    float2 v = g_w400[m];
    if (INV) v.y = -v.y;
    return v;
}

// ----------------------------- FFT-20 (registers): n=20, j=5*j1+j2, k=k1+4*k2 ------
// HZ:   inputs a[5..14] are identically zero (never read).
// CROP: only outputs k in {0..4, 15..19} are produced (a[5..14] left garbage).
template<bool INV, bool HZ, bool CROP>
__device__ __forceinline__ void fft20(float2* a){
    float2 t[20];
    #pragma unroll
    for (int j2=0;j2<5;j2++){
        float2 y0,y1,y2,y3;
        if (HZ){
            float2 x0=a[j2], x3=a[15+j2];
            y0 = make_float2(x0.x+x3.x, x0.y+x3.y);
            y2 = make_float2(x0.x-x3.x, x0.y-x3.y);
            if (!INV){ y1 = make_float2(x0.x - x3.y, x0.y + x3.x);   // x0 + i x3
                       y3 = make_float2(x0.x + x3.y, x0.y - x3.x); } // x0 - i x3
            else     { y1 = make_float2(x0.x + x3.y, x0.y - x3.x);
                       y3 = make_float2(x0.x - x3.y, x0.y + x3.x); }
        } else {
            float2 x0=a[j2], x1=a[5+j2], x2=a[10+j2], x3=a[15+j2];
            float2 s02=make_float2(x0.x+x2.x, x0.y+x2.y);
            float2 d02=make_float2(x0.x-x2.x, x0.y-x2.y);
            float2 s13=make_float2(x1.x+x3.x, x1.y+x3.y);
            float2 d13=make_float2(x1.x-x3.x, x1.y-x3.y);
            y0=make_float2(s02.x+s13.x, s02.y+s13.y);
            y2=make_float2(s02.x-s13.x, s02.y-s13.y);
            if (!INV){ y1=make_float2(d02.x+d13.y, d02.y-d13.x);   // d02 - i*d13
                       y3=make_float2(d02.x-d13.y, d02.y+d13.x); } // d02 + i*d13
            else     { y1=make_float2(d02.x-d13.y, d02.y+d13.x);
                       y3=make_float2(d02.x+d13.y, d02.y-d13.x); }
        }
        t[j2]    = y0;                                   // W20^m = W400^{20m} (uniform/broadcast)
        t[5+j2]  = cmul(y1, TW<INV>(20*j2));
        t[10+j2] = cmul(y2, TW<INV>(40*j2));
        t[15+j2] = cmul(y3, TW<INV>(60*j2));
    }
    const float C1f= 0.30901699437494742f, S1f=0.95105651629515357f;
    const float C2f=-0.80901699437494745f, S2f=0.58778525229247313f;
    const float si = INV ? 1.f : -1.f;
    const float2 w1=make_float2(C1f, si*S1f), w2=make_float2(C2f, si*S2f);
    const float2 w3=make_float2(C2f,-si*S2f), w4=make_float2(C1f,-si*S1f);
    #pragma unroll
    for (int k1=0;k1<4;k1++){
        float2 b0=t[k1*5], b1=t[k1*5+1], b2=t[k1*5+2], b3=t[k1*5+3], b4=t[k1*5+4];
        float2 y0=make_float2(b0.x+b1.x+b2.x+b3.x+b4.x, b0.y+b1.y+b2.y+b3.y+b4.y);
        a[k1]=y0;
        if (!CROP || k1==0){
            float2 y1=b0; y1=cfma(y1,b1,w1); y1=cfma(y1,b2,w2); y1=cfma(y1,b3,w3); y1=cfma(y1,b4,w4);
            a[k1+4]=y1;
        }
        if (!CROP){
            float2 y2=b0; y2=cfma(y2,b1,w2); y2=cfma(y2,b2,w4); y2=cfma(y2,b3,w1); y2=cfma(y2,b4,w3);
            a[k1+8]=y2;
        }
        if (!CROP || k1==3){
            float2 y3=b0; y3=cfma(y3,b1,w3); y3=cfma(y3,b2,w1); y3=cfma(y3,b3,w4); y3=cfma(y3,b4,w2);
            a[k1+12]=y3;
        }
        float2 y4=b0; y4=cfma(y4,b1,w4); y4=cfma(y4,b2,w3); y4=cfma(y4,b3,w2); y4=cfma(y4,b4,w1);
        a[k1+16]=y4;
    }
}

// ----------------------------- FFT-400 (warp, 20 active lanes): 20x20 four-step ----
// Inter-stage twiddles W400^{lane*k1} built incrementally in registers:
// 4 exact anchor loads + chained complex multiplies (<=2 chained per value).
template<bool INV, bool HZ, bool CROP>
__device__ void fft400(float2* __restrict__ lin, float2* __restrict__ tmp, int lane){
    __syncwarp();
    float2 r[20];
    if (lane < 20){
        if (HZ){
            #pragma unroll
            for (int j1=0;j1<5;j1++)  r[j1]=lin[j1*20+lane];
            #pragma unroll
            for (int j1=15;j1<20;j1++) r[j1]=lin[j1*20+lane];
        } else {
            #pragma unroll
            for (int j1=0;j1<20;j1++) r[j1]=lin[j1*20+lane];
        }
        fft20<INV,HZ,false>(r);                          // over j1
        // incremental twiddles (lane-scattered loads reduced 19 -> 4)
        {
            float2 Wa = TW<INV>(lane);
            float2 A5 = TW<INV>(5*lane);
            float2 A10= TW<INV>(10*lane);
            float2 A15= TW<INV>(15*lane);
            float2 W2 = cmul(Wa,Wa);
            float2 W3 = cmul(W2,Wa);
            float2 W4 = cmul(W3,Wa);
            r[1]=cmul(r[1],Wa);  r[2]=cmul(r[2],W2);
            r[3]=cmul(r[3],W3);  r[4]=cmul(r[4],W4);
            r[5]=cmul(r[5],A5);
            r[6]=cmul(r[6],cmul(A5,Wa));   r[7]=cmul(r[7],cmul(A5,W2));
            r[8]=cmul(r[8],cmul(A5,W3));   r[9]=cmul(r[9],cmul(A5,W4));
            r[10]=cmul(r[10],A10);
            r[11]=cmul(r[11],cmul(A10,Wa)); r[12]=cmul(r[12],cmul(A10,W2));
            r[13]=cmul(r[13],cmul(A10,W3)); r[14]=cmul(r[14],cmul(A10,W4));
            r[15]=cmul(r[15],A15);
            r[16]=cmul(r[16],cmul(A15,Wa)); r[17]=cmul(r[17],cmul(A15,W2));
            r[18]=cmul(r[18],cmul(A15,W3)); r[19]=cmul(r[19],cmul(A15,W4));
        }
        #pragma unroll
        for (int k1=0;k1<20;k1++) tmp[k1*21+lane]=r[k1];
    }
    __syncwarp();
    if (lane < 20){
        #pragma unroll
        for (int j2=0;j2<20;j2++) r[j2]=tmp[lane*21+j2];
        fft20<INV,false,CROP>(r);                        // over j2
        #pragma unroll
        for (int k2=0;k2<20;k2++)
            if (!CROP || k2<5 || k2>=15) lin[k2*20+lane]=r[k2]; // X[k1+20*k2]
    }
    __syncwarp();
}

#define WPB 4  // warps (transforms) per block for row-FFT kernels

// ----------------------------- init: twiddles + zero histogram -----------------------------
__global__ void kInit(float* out){
    int k = threadIdx.x;
    if (k < 400){
        double ang = -2.0*PI_D*(double)k/400.0;
        g_w400[k] = make_float2((float)cos(ang), (float)sin(ang));
    }
    if (k < 11) out[1250+k] = 0.f;
}

// ----------------------------- transpose transfer functions (tiled) -----------------------------
__global__ void kHT(const float2* __restrict__ t0, const float2* __restrict__ t1,
                    const float2* __restrict__ t2){
    __shared__ float2 tile[32][33];
    int m = blockIdx.z;
    const float2* src = (m==0)? t0 : (m==1)? t1 : t2;
    int r0 = blockIdx.y*32, k0 = blockIdx.x*32;
    int tx = threadIdx.x, ty = threadIdx.y;   // 32 x 8
    for (int yy=ty; yy<32; yy+=8){
        int r = r0+yy, k = k0+tx;
        if (r<400 && k<400) tile[yy][tx] = src[r*400+k];
    }
    __syncthreads();
    for (int yy=ty; yy<32; yy+=8){
        int k = k0+yy, r = r0+tx;
        if (r<400 && k<400) g_HT[(size_t)m*160000 + k*400 + r] = tile[tx][yy];
    }
}

// ----------------------------- W1 transpose + row sums -----------------------------
__global__ void kT(const float* __restrict__ W1){
    int idx = blockIdx.x*256 + threadIdx.x;
    if (idx >= 625*512) return;
    int p = idx>>9, hh = idx&511;
    g_W1T[idx] = W1[hh*625+p];
}
__global__ void kR1(const float* __restrict__ W1){   // grid 512, block 128
    __shared__ float red[128];
    int hh = blockIdx.x, tid = threadIdx.x;
    float s = 0.f;
    for (int p=tid; p<625; p+=128) s += W1[hh*625+p];
    red[tid] = s;
    __syncthreads();
    for (int st=64; st>0; st>>=1){
        if (tid<st) red[tid]+=red[tid+st];
        __syncthreads();
    }
    if (tid==0) g_R1[hh] = red[0];
}

// ----------------------------- A0: real input -> row FFT -----------------------------
__global__ void kA0(const float* __restrict__ x){
    __shared__ float2 s_lin[WPB][400];
    __shared__ float2 s_tmp[WPB][421];
    int w = threadIdx.x>>5, lane = threadIdx.x&31;
    int idx = blockIdx.x*WPB + w;
    int b = idx/200, c = idx%200;
    int i = (c<100)? c+100 : c-100;                 // logical row
    const float* xr = x + ((size_t)b*200 + i)*200;
    float2* lin = s_lin[w]; float2* tmp = s_tmp[w];
    for (int mm=lane; mm<200; mm+=32){
        int m = (mm<100)? mm : mm+200;
        float v = (mm<100)? xr[mm+100] : xr[mm-100];
        lin[m] = make_float2(v, 0.f);
    }
    fft400<false,true,false>(lin,tmp,lane);
    float2* out = g_S + ((size_t)b*200+c)*400;
    for (int m=lane;m<400;m+=32) out[m]=lin[m];
}

// ----------------------------- B (warp-private): col FFT * trans * col IFFT --------
// One block: 8 adjacent freq-columns of one image, 128 threads (4 warps).
// Static smem: col[8][401] + tmp[4][421]. Each warp runs 2 columns privately.
__global__ void __launch_bounds__(128) kB(int hm){
    __shared__ float2 colb[8][401];
    __shared__ float2 tmpb[4][421];
    int b  = blockIdx.x / 50;
    int k0 = (blockIdx.x % 50) * 8;
    int tid = threadIdx.x;
    const float2* Sb = g_S + (size_t)b*200*400;
    const float2* HT = g_HT + (size_t)hm*160000;

    // stage in (coalesced): col[kl][r], r in [0,100) U [300,400)
    for (int idx=tid; idx<200*8; idx+=128){
        int c = idx>>3, kl = idx&7;
        float2 v = Sb[c*400 + k0 + kl];
        int r = (c<100)? c : c+200;
        colb[kl][r] = v;
    }
    __syncthreads();

    int w = tid>>5, lane = tid&31;
    #pragma unroll
    for (int s=0; s<2; s++){
        int kl = 2*w + s;
        float2* col = colb[kl];
        fft400<false,true,false>(col, tmpb[w], lane);           // fwd, half-zero input
        const float2* ht = HT + (size_t)(k0+kl)*400;
        for (int r=lane; r<400; r+=32) col[r] = cmul(col[r], ht[r]);  // coalesced
        fft400<true,false,true>(col, tmpb[w], lane);            // inv, cropped output
    }
    __syncthreads();

    // stage out (coalesced), crop rows, scale 1/400
    float2* S2b = g_S2 + (size_t)b*200*400;
    const float sc = 1.f/400.f;
    for (int idx=tid; idx<200*8; idx+=128){
        int c = idx>>3, kl = idx&7;
        int r = (c<100)? c : c+200;
        float2 v = colb[kl][r];
        S2b[c*400 + k0 + kl] = make_float2(v.x*sc, v.y*sc);
    }
}

// ----------------------------- C: row IFFT + (phasor) + row FFT (fused) -----------
__global__ void kC(const float* __restrict__ ph){   // ph == nullptr for first boundary
    __shared__ float2 s_lin[WPB][400];
    __shared__ float2 s_tmp[WPB][421];
    int w = threadIdx.x>>5, lane = threadIdx.x&31;
    int idx = blockIdx.x*WPB + w;
    int b = idx/200, c = idx%200;
    float2* lin = s_lin[w]; float2* tmp = s_tmp[w];
    const float2* S2b = g_S2 + ((size_t)b*200+c)*400;
    for (int m=lane;m<400;m+=32) lin[m]=S2b[m];
    fft400<true,false,true>(lin,tmp,lane);          // cropped inverse
    int i = (c<100)? c+100 : c-100;                 // logical row
    const float sc = 1.f/400.f;
    float2 keep[7];
    #pragma unroll
    for (int kk=0;kk<7;kk++){
        int cc = lane + kk*32;
        if (cc < 200){
            int rc = (cc<100)? cc : cc+200;
            float2 v = lin[rc];
            v.x *= sc; v.y *= sc;
            if (ph){
                int j = (cc<100)? cc+100 : cc-100;
                float p = ph[i*200+j];
                float sv, cv;
                sincospif(2.f*(sinf(p)+1.f), &sv, &cv); // e^{i*2*pi*(sin(p)+1)}
                v = cmul(v, make_float2(cv, sv));
            }
            keep[kk] = v;
        }
    }
    __syncwarp();
    #pragma unroll
    for (int kk=0;kk<7;kk++){
        int cc = lane + kk*32;
        if (cc < 200){
            int rc = (cc<100)? cc : cc+200;
            lin[rc] = keep[kk];
        }
    }
    fft400<false,true,false>(lin,tmp,lane);   // half-zero input: middle never read
    float2* out = g_S + ((size_t)b*200+c)*400;
    for (int m=lane;m<400;m+=32) out[m]=lin[m];
}

// ----------------------------- CF: row IFFT -> intensity (logical layout) ----------
__global__ void kCF(){
    __shared__ float2 s_lin[WPB][400];
    __shared__ float2 s_tmp[WPB][421];
    int w = threadIdx.x>>5, lane = threadIdx.x&31;
    int idx = blockIdx.x*WPB + w;
    int b = idx/200, c = idx%200;
    float2* lin = s_lin[w]; float2* tmp = s_tmp[w];
    const float2* S2b = g_S2 + ((size_t)b*200+c)*400;
    for (int m=lane;m<400;m+=32) lin[m]=S2b[m];
    fft400<true,false,true>(lin,tmp,lane);          // cropped inverse
    int i = (c<100)? c+100 : c-100;
    float* Ib = g_I + (size_t)b*40000 + i*200;
    const float sc = 1.f/400.f;
    for (int cc=lane;cc<200;cc+=32){
        int rc = (cc<100)? cc : cc+200;
        int j  = (cc<100)? cc+100 : cc-100;
        float vx = lin[rc].x*sc, vy = lin[rc].y*sc;
        Ib[j] = vx*vx + vy*vy;
    }
}

// ----------------------------- pooling: 8x8 mean -> [p][b], p-fastest mapping ------
__global__ void kPool(){
    int idx = blockIdx.x*256 + threadIdx.x;
    if (idx >= 20000) return;
    int b = idx / 625, p = idx % 625;     // adjacent threads: adjacent p -> coalesced reads
    int mi = p/25, mj = p%25;
    const float* base = g_I + (size_t)b*40000 + mi*8*200 + mj*8;
    float s = 0.f;
    #pragma unroll
    for (int u=0;u<8;u++)
        #pragma unroll
        for (int v=0;v<8;v++) s += base[u*200+v];
    g_pool[p*32+b] = s*(1.f/64.f);
}

// ----------------------------- per-window MLP + voting -----------------------------
#define HSTR 513    // padded hid stride (bank-conflict-free)
__global__ void __launch_bounds__(256) kWin(
                     const float* __restrict__ b1, const float* __restrict__ W2,
                     const float* __restrict__ b2, const float* __restrict__ gamma,
                     const float* __restrict__ beta, float* __restrict__ out)
{
    extern __shared__ float dsm[];
    float* swin = dsm;                    // [cell][b] up to 25*32
    float* hid  = dsm + 800;              // [b][hh] 32*HSTR
    float* lg   = dsm + 800 + 32*HSTR;    // [b][o]  32*10
    __shared__ double red1[256], red2[256];
    __shared__ int   pidx[25];
    __shared__ float s_inv, s_c0;
    __shared__ int   s_a[32];
    __shared__ float s_delta[32];

    int wI = blockIdx.x;
    int i = wI/25, j = wI%25;
    int wr = min(5, 25-i), wc = min(5, 25-j);
    int cells = wr*wc;
    int tid = threadIdx.x;
    if (tid < cells) pidx[tid] = (i + tid/wc)*25 + (j + tid%wc);
    __syncthreads();

    double s1 = 0.0, s2 = 0.0;
    for (int q=tid; q<cells*32; q+=256){
        int cell = q>>5, b = q&31;
        float v = g_pool[pidx[cell]*32 + b];
        swin[q] = v;
        s1 += v; s2 += (double)v*(double)v;
    }
    red1[tid]=s1; red2[tid]=s2;
    __syncthreads();
    for (int st=128; st>0; st>>=1){
        if (tid<st){ red1[tid]+=red1[tid+st]; red2[tid]+=red2[tid+st]; }
        __syncthreads();
    }
    if (tid == 0){
        double mu  = red1[0]/20000.0;
        double var = red2[0]/20000.0 - mu*mu;
        float inv = gamma[0]/(float)sqrt(var + 1e-5);
        s_inv = inv;
        s_c0  = beta[0] - (float)mu*inv;
    }
    __syncthreads();
    float inv = s_inv, c0 = s_c0;

    // hid[b][hh] = relu(c0*R1 + inv*<win,W1win> + b1); 8 batches per thread.
    for (int it=0; it<8; it++){
        int task = it*256 + tid;          // 2048 tasks = 4 bgroups x 512 hh
        int hh = task & 511, bg = task >> 9;
        float acc[8];
        #pragma unroll
        for (int u=0;u<8;u++) acc[u]=0.f;
        for (int cell=0; cell<cells; cell++){
            float wv = g_W1T[pidx[cell]*512+hh];
            const float* sw = swin + cell*32 + bg*8;
            #pragma unroll
            for (int u=0;u<8;u++) acc[u] = fmaf(sw[u], wv, acc[u]);
        }
        float base = fmaf(c0, g_R1[hh], b1[hh]);
        #pragma unroll
        for (int u=0;u<8;u++){
            float pre = fmaf(inv, acc[u], base);
            hid[(bg*8+u)*HSTR + hh] = fmaxf(pre, 0.f);
        }
    }
    __syncthreads();

    for (int t=tid; t<320; t+=256){
        int b = t/10, oo = t%10;
        float acc = b2[oo];
        const float* hb = hid + b*HSTR;
        const float* wv = W2 + oo*512;
        for (int hh=0; hh<512; hh++) acc = fmaf(hb[hh], wv[hh], acc);
        lg[b*10+oo] = acc;
    }
    __syncthreads();

    if (tid < 32){
        int b = tid;
        float lmax = lg[b*10], lmin = lg[b*10];
        int am = 0;
        for (int oo=1;oo<10;oo++){
            float v = lg[b*10+oo];
            if (v > lmax){ lmax = v; am = oo; }
            if (v < lmin)  lmin = v;
        }
        float se = 0.f;
        for (int oo=0;oo<10;oo++) se += expf(lg[b*10+oo]-lmax);
        s_a[b] = am;
        s_delta[b] = (1.f - expf(lmin-lmax))/se;  // pmax - pmin
    }
    __syncthreads();
    if (tid == 0){
        int votes[11];
        for (int k=0;k<11;k++) votes[k]=0;
        for (int b=0;b<32;b++) votes[s_a[b]]++;
        int f0 = 0, best = votes[0];
        for (int k=1;k<11;k++) if (votes[k] > best){ best = votes[k]; f0 = k; }
        float sum = 0.f; int cnt = 0;
        for (int b=0;b<32;b++)
            if (s_a[b]==f0 && s_delta[b]!=0.f){ sum += s_delta[b]; cnt++; }
        int fin;
        if (cnt > 0){ float d1 = sum/(float)cnt; fin = (d1 < 0.2f) ? 0 : f0+1; }
        else fin = f0+1;   // delta1 = NaN; NaN < THR is false
        out[wI]       = (fin==0) ? 0.f : (float)fin;
        out[625+wI]   = (fin!=0) ? 1.f : 0.f;
        atomicAdd(&out[1250+fin], 1.0f);   // exact integer counts -> deterministic
    }
}

// ----------------------------- launch -----------------------------
extern "C" void kernel_launch(void* const* d_in, const int* in_sizes, int n_in,
                              void* d_out, int out_size)
{
    int o = (n_in >= 12 && in_sizes[1] == 1) ? 1 : 0;  // skip batch_size scalar if present
    const float*  x     = (const float*) d_in[0];
    const float2* h     = (const float2*)d_in[1+o];
    const float2* h_pro = (const float2*)d_in[2+o];
    const float2* h_det = (const float2*)d_in[3+o];
    const float*  phase = (const float*) d_in[4+o];
    const float*  W1    = (const float*) d_in[5+o];
    const float*  b1    = (const float*) d_in[6+o];
    const float*  W2    = (const float*) d_in[7+o];
    const float*  b2    = (const float*) d_in[8+o];
    const float*  gamma = (const float*) d_in[9+o];
    const float*  beta  = (const float*) d_in[10+o];
    float* out = (float*)d_out;

    cudaFuncSetAttribute(kWin, cudaFuncAttributeMaxDynamicSharedMemorySize,
                         (800 + 32*HSTR + 320)*4);

    kInit<<<1,512>>>(out);
    kHT <<<dim3(13,13,3),dim3(32,8)>>>(h_pro, h, h_det);   // [0]=h_pro, [1]=h, [2]=h_det
    kT  <<<1250,256>>>(W1);
    kR1 <<<512,128>>>(W1);

    kA0 <<<1600,128>>>(x);
    kB  <<<1600,128>>>(0);                 // h_pro
    kC  <<<1600,128>>>(nullptr);
    for (int l=0; l<4; l++){
        kB <<<1600,128>>>(1);              // h (transposed once, reused 4x)
        kC <<<1600,128>>>(phase + (size_t)l*40000);
    }
    kB  <<<1600,128>>>(2);                 // h_det
    kCF <<<1600,128>>>();

    kPool<<<79,256>>>();

    kWin<<<625,256,(800 + 32*HSTR + 320)*4>>>(b1, W2, b2, gamma, beta, out);
}

// round 7
// speedup vs baseline: 1.9154x; 1.1139x over previous
#include <cuda_runtime.h>
#include <math.h>

#define PI_D 3.14159265358979323846

// ----------------------------- scratch (device globals) -----------------------------
__device__ __align__(16) float2 g_S [32*200*400];   // row-FFT'd field, compact rows
__device__ __align__(16) float2 g_S2[32*200*400];   // after col FFT * trans * IFFT
__device__ float2 g_HT[3*400*400];    // transposed transfer functions [m][k][r]
__device__ float2 g_PH[4*200*200];    // precomputed layer phasors [l][i][j]
__device__ float  g_I [32*200*200];   // final intensity, logical layout
__device__ float  g_pool[625*32];     // pooled [p][b]
__device__ float  g_W1T[625*512];     // W1 transposed [p][hh]
__device__ float  g_R1[512];          // row sums of W1
__device__ float2 g_w400[400];        // e^{-2*pi*i*k/400}, fp64-initialized

// ----------------------------- complex helpers -----------------------------
__device__ __forceinline__ float2 cmul(float2 a, float2 b){
    return make_float2(fmaf(a.x,b.x,-a.y*b.y), fmaf(a.x,b.y, a.y*b.x));
}
__device__ __forceinline__ float2 cfma(float2 r, float2 a, float2 w){
    r.x = fmaf(a.x,w.x, fmaf(-a.y,w.y,r.x));
    r.y = fmaf(a.x,w.y, fmaf( a.y,w.x,r.y));
    return r;
}
template<bool INV>
__device__ __forceinline__ float2 TW(int m){   // W400^m (conj if INV)
    float2 v = g_w400[m];
    if (INV) v.y = -v.y;
    return v;
}

// ----------------------------- FFT-20 (registers): n=20, j=5*j1+j2, k=k1+4*k2 ------
// HZ:   inputs a[5..14] are identically zero (never read).
// CROP: only outputs k in {0..4, 15..19} are produced (a[5..14] left garbage).
template<bool INV, bool HZ, bool CROP>
__device__ __forceinline__ void fft20(float2* a){
    float2 t[20];
    #pragma unroll
    for (int j2=0;j2<5;j2++){
        float2 y0,y1,y2,y3;
        if (HZ){
            float2 x0=a[j2], x3=a[15+j2];
            y0 = make_float2(x0.x+x3.x, x0.y+x3.y);
            y2 = make_float2(x0.x-x3.x, x0.y-x3.y);
            if (!INV){ y1 = make_float2(x0.x - x3.y, x0.y + x3.x);   // x0 + i x3
                       y3 = make_float2(x0.x + x3.y, x0.y - x3.x); } // x0 - i x3
            else     { y1 = make_float2(x0.x + x3.y, x0.y - x3.x);
                       y3 = make_float2(x0.x - x3.y, x0.y + x3.x); }
        } else {
            float2 x0=a[j2], x1=a[5+j2], x2=a[10+j2], x3=a[15+j2];
            float2 s02=make_float2(x0.x+x2.x, x0.y+x2.y);
            float2 d02=make_float2(x0.x-x2.x, x0.y-x2.y);
            float2 s13=make_float2(x1.x+x3.x, x1.y+x3.y);
            float2 d13=make_float2(x1.x-x3.x, x1.y-x3.y);
            y0=make_float2(s02.x+s13.x, s02.y+s13.y);
            y2=make_float2(s02.x-s13.x, s02.y-s13.y);
            if (!INV){ y1=make_float2(d02.x+d13.y, d02.y-d13.x);   // d02 - i*d13
                       y3=make_float2(d02.x-d13.y, d02.y+d13.x); } // d02 + i*d13
            else     { y1=make_float2(d02.x-d13.y, d02.y+d13.x);
                       y3=make_float2(d02.x+d13.y, d02.y-d13.x); }
        }
        t[j2]    = y0;                                   // W20^m = W400^{20m} (broadcast)
        t[5+j2]  = cmul(y1, TW<INV>(20*j2));
        t[10+j2] = cmul(y2, TW<INV>(40*j2));
        t[15+j2] = cmul(y3, TW<INV>(60*j2));
    }
    const float C1f= 0.30901699437494742f, S1f=0.95105651629515357f;
    const float C2f=-0.80901699437494745f, S2f=0.58778525229247313f;
    const float si = INV ? 1.f : -1.f;
    const float2 w1=make_float2(C1f, si*S1f), w2=make_float2(C2f, si*S2f);
    const float2 w3=make_float2(C2f,-si*S2f), w4=make_float2(C1f,-si*S1f);
    #pragma unroll
    for (int k1=0;k1<4;k1++){
        float2 b0=t[k1*5], b1=t[k1*5+1], b2=t[k1*5+2], b3=t[k1*5+3], b4=t[k1*5+4];
        float2 y0=make_float2(b0.x+b1.x+b2.x+b3.x+b4.x, b0.y+b1.y+b2.y+b3.y+b4.y);
        a[k1]=y0;
        if (!CROP || k1==0){
            float2 y1=b0; y1=cfma(y1,b1,w1); y1=cfma(y1,b2,w2); y1=cfma(y1,b3,w3); y1=cfma(y1,b4,w4);
            a[k1+4]=y1;
        }
        if (!CROP){
            float2 y2=b0; y2=cfma(y2,b1,w2); y2=cfma(y2,b2,w4); y2=cfma(y2,b3,w1); y2=cfma(y2,b4,w3);
            a[k1+8]=y2;
        }
        if (!CROP || k1==3){
            float2 y3=b0; y3=cfma(y3,b1,w3); y3=cfma(y3,b2,w1); y3=cfma(y3,b3,w4); y3=cfma(y3,b4,w2);
            a[k1+12]=y3;
        }
        float2 y4=b0; y4=cfma(y4,b1,w4); y4=cfma(y4,b2,w3); y4=cfma(y4,b3,w2); y4=cfma(y4,b4,w1);
        a[k1+16]=y4;
    }
}

// ----------------------------- FFT-400 (warp, 20 active lanes): 20x20 four-step ----
template<bool INV, bool HZ, bool CROP>
__device__ void fft400(float2* __restrict__ lin, float2* __restrict__ tmp, int lane){
    __syncwarp();
    float2 r[20];
    if (lane < 20){
        if (HZ){
            #pragma unroll
            for (int j1=0;j1<5;j1++)  r[j1]=lin[j1*20+lane];
            #pragma unroll
            for (int j1=15;j1<20;j1++) r[j1]=lin[j1*20+lane];
        } else {
            #pragma unroll
            for (int j1=0;j1<20;j1++) r[j1]=lin[j1*20+lane];
        }
        fft20<INV,HZ,false>(r);                          // over j1
        // incremental twiddles (lane-scattered loads reduced 19 -> 4)
        {
            float2 Wa = TW<INV>(lane);
            float2 A5 = TW<INV>(5*lane);
            float2 A10= TW<INV>(10*lane);
            float2 A15= TW<INV>(15*lane);
            float2 W2 = cmul(Wa,Wa);
            float2 W3 = cmul(W2,Wa);
            float2 W4 = cmul(W3,Wa);
            r[1]=cmul(r[1],Wa);  r[2]=cmul(r[2],W2);
            r[3]=cmul(r[3],W3);  r[4]=cmul(r[4],W4);
            r[5]=cmul(r[5],A5);
            r[6]=cmul(r[6],cmul(A5,Wa));   r[7]=cmul(r[7],cmul(A5,W2));
            r[8]=cmul(r[8],cmul(A5,W3));   r[9]=cmul(r[9],cmul(A5,W4));
            r[10]=cmul(r[10],A10);
            r[11]=cmul(r[11],cmul(A10,Wa)); r[12]=cmul(r[12],cmul(A10,W2));
            r[13]=cmul(r[13],cmul(A10,W3)); r[14]=cmul(r[14],cmul(A10,W4));
            r[15]=cmul(r[15],A15);
            r[16]=cmul(r[16],cmul(A15,Wa)); r[17]=cmul(r[17],cmul(A15,W2));
            r[18]=cmul(r[18],cmul(A15,W3)); r[19]=cmul(r[19],cmul(A15,W4));
        }
        #pragma unroll
        for (int k1=0;k1<20;k1++) tmp[k1*21+lane]=r[k1];
    }
    __syncwarp();
    if (lane < 20){
        #pragma unroll
        for (int j2=0;j2<20;j2++) r[j2]=tmp[lane*21+j2];
        fft20<INV,false,CROP>(r);                        // over j2
        #pragma unroll
        for (int k2=0;k2<20;k2++)
            if (!CROP || k2<5 || k2>=15) lin[k2*20+lane]=r[k2]; // X[k1+20*k2]
    }
    __syncwarp();
}

#define WPB 4  // warps (transforms) per block for row-FFT kernels

// ----------------------------- init: twiddles + zero histogram -----------------------------
__global__ void kInit(float* out){
    int k = threadIdx.x;
    if (k < 400){
        double ang = -2.0*PI_D*(double)k/400.0;
        g_w400[k] = make_float2((float)cos(ang), (float)sin(ang));
    }
    if (k < 11) out[1250+k] = 0.f;
}

// ----------------------------- precompute layer phasors (unique (l,i,j) only) ------
__global__ void kPrep(const float* __restrict__ phase){
    int idx = blockIdx.x*256 + threadIdx.x;
    if (idx >= 4*40000) return;
    float p = phase[idx];
    float sv, cv;
    sincospif(2.f*(sinf(p)+1.f), &sv, &cv);   // e^{i*2*pi*(sin(p)+1)}
    g_PH[idx] = make_float2(cv, sv);
}

// ----------------------------- transpose transfer functions (tiled) -----------------------------
__global__ void kHT(const float2* __restrict__ t0, const float2* __restrict__ t1,
                    const float2* __restrict__ t2){
    __shared__ float2 tile[32][33];
    int m = blockIdx.z;
    const float2* src = (m==0)? t0 : (m==1)? t1 : t2;
    int r0 = blockIdx.y*32, k0 = blockIdx.x*32;
    int tx = threadIdx.x, ty = threadIdx.y;   // 32 x 8
    for (int yy=ty; yy<32; yy+=8){
        int r = r0+yy, k = k0+tx;
        if (r<400 && k<400) tile[yy][tx] = src[r*400+k];
    }
    __syncthreads();
    for (int yy=ty; yy<32; yy+=8){
        int k = k0+yy, r = r0+tx;
        if (r<400 && k<400) g_HT[(size_t)m*160000 + k*400 + r] = tile[tx][yy];
    }
}

// ----------------------------- W1 transpose (tiled) + row sums -----------------------------
__global__ void kT(const float* __restrict__ W1){
    __shared__ float tile[32][33];
    int p0 = blockIdx.x*32, h0 = blockIdx.y*32;
    int tx = threadIdx.x, ty = threadIdx.y;   // 32 x 8
    for (int yy=ty; yy<32; yy+=8){
        int hh = h0+yy, p = p0+tx;
        if (hh<512 && p<625) tile[yy][tx] = W1[hh*625+p];
    }
    __syncthreads();
    for (int yy=ty; yy<32; yy+=8){
        int p = p0+yy, hh = h0+tx;
        if (p<625 && hh<512) g_W1T[p*512+hh] = tile[tx][yy];
    }
}
__global__ void kR1(const float* __restrict__ W1){   // grid 512, block 128
    __shared__ float red[128];
    int hh = blockIdx.x, tid = threadIdx.x;
    float s = 0.f;
    for (int p=tid; p<625; p+=128) s += W1[hh*625+p];
    red[tid] = s;
    __syncthreads();
    for (int st=64; st>0; st>>=1){
        if (tid<st) red[tid]+=red[tid+st];
        __syncthreads();
    }
    if (tid==0) g_R1[hh] = red[0];
}

// ----------------------------- A0: real input -> row FFT -----------------------------
__global__ void kA0(const float* __restrict__ x){
    __shared__ __align__(16) float2 s_lin[WPB][400];
    __shared__ float2 s_tmp[WPB][421];
    int w = threadIdx.x>>5, lane = threadIdx.x&31;
    int idx = blockIdx.x*WPB + w;
    int b = idx/200, c = idx%200;
    int i = (c<100)? c+100 : c-100;                 // logical row
    const float4* xr4 = (const float4*)(x + ((size_t)b*200 + i)*200);
    float2* lin = s_lin[w]; float2* tmp = s_tmp[w];
    if (lane < 25){
        float4 v = xr4[25+lane];                    // x[100..199] -> lin[0..99]
        lin[4*lane  ] = make_float2(v.x,0.f);
        lin[4*lane+1] = make_float2(v.y,0.f);
        lin[4*lane+2] = make_float2(v.z,0.f);
        lin[4*lane+3] = make_float2(v.w,0.f);
        float4 u = xr4[lane];                       // x[0..99]   -> lin[300..399]
        lin[300+4*lane  ] = make_float2(u.x,0.f);
        lin[300+4*lane+1] = make_float2(u.y,0.f);
        lin[300+4*lane+2] = make_float2(u.z,0.f);
        lin[300+4*lane+3] = make_float2(u.w,0.f);
    }
    fft400<false,true,false>(lin,tmp,lane);
    float4* out4 = (float4*)(g_S + ((size_t)b*200+c)*400);
    const float4* lin4 = (const float4*)lin;
    for (int m4=lane;m4<200;m4+=32) out4[m4]=lin4[m4];
}

// ----------------------------- B (warp-private): col FFT * trans * col IFFT --------
// One block: 8 adjacent freq-columns of one image, 128 threads (4 warps).
__global__ void __launch_bounds__(128) kB(int hm){
    __shared__ __align__(16) float2 colb[8][401];
    __shared__ float2 tmpb[4][421];
    int b  = blockIdx.x / 50;
    int k0 = (blockIdx.x % 50) * 8;
    int tid = threadIdx.x;
    const float4* Sb4 = (const float4*)(g_S + (size_t)b*200*400);
    const float2* HT = g_HT + (size_t)hm*160000;

    // stage in (float4 = 2 complex): col[kl][r], r in [0,100) U [300,400)
    for (int idx=tid; idx<800; idx+=128){
        int c = idx>>2, q = idx&3;
        float4 v = Sb4[c*200 + (k0>>1) + q];
        int r = (c<100)? c : c+200;
        colb[2*q  ][r] = make_float2(v.x,v.y);
        colb[2*q+1][r] = make_float2(v.z,v.w);
    }
    __syncthreads();

    int w = tid>>5, lane = tid&31;
    #pragma unroll
    for (int s=0; s<2; s++){
        int kl = 2*w + s;
        float2* col = colb[kl];
        fft400<false,true,false>(col, tmpb[w], lane);           // fwd, half-zero input
        const float2* ht = HT + (size_t)(k0+kl)*400;
        for (int r=lane; r<400; r+=32) col[r] = cmul(col[r], ht[r]);  // coalesced
        fft400<true,false,true>(col, tmpb[w], lane);            // inv, cropped output
    }
    __syncthreads();

    // stage out (float4), crop rows, scale 1/400
    float4* S2b4 = (float4*)(g_S2 + (size_t)b*200*400);
    const float sc = 1.f/400.f;
    for (int idx=tid; idx<800; idx+=128){
        int c = idx>>2, q = idx&3;
        int r = (c<100)? c : c+200;
        float2 v0 = colb[2*q  ][r];
        float2 v1 = colb[2*q+1][r];
        S2b4[c*200 + (k0>>1) + q] = make_float4(v0.x*sc, v0.y*sc, v1.x*sc, v1.y*sc);
    }
}

// ----------------------------- C: row IFFT + (phasor) + row FFT (fused) -----------
__global__ void kC(int l){   // l < 0: no phasor (first boundary)
    __shared__ __align__(16) float2 s_lin[WPB][400];
    __shared__ float2 s_tmp[WPB][421];
    int w = threadIdx.x>>5, lane = threadIdx.x&31;
    int idx = blockIdx.x*WPB + w;
    int b = idx/200, c = idx%200;
    float2* lin = s_lin[w]; float2* tmp = s_tmp[w];
    const float4* S4 = (const float4*)(g_S2 + ((size_t)b*200+c)*400);
    float4* lin4 = (float4*)lin;
    for (int m4=lane;m4<200;m4+=32) lin4[m4]=S4[m4];
    fft400<true,false,true>(lin,tmp,lane);          // cropped inverse
    int i = (c<100)? c+100 : c-100;                 // logical row
    const float2* phrow = (l>=0)? (g_PH + (size_t)l*40000 + i*200) : nullptr;
    const float sc = 1.f/400.f;
    float2 keep[7];
    #pragma unroll
    for (int kk=0;kk<7;kk++){
        int cc = lane + kk*32;
        if (cc < 200){
            int rc = (cc<100)? cc : cc+200;
            float2 v = lin[rc];
            v.x *= sc; v.y *= sc;
            if (phrow){
                int j = (cc<100)? cc+100 : cc-100;
                v = cmul(v, phrow[j]);
            }
            keep[kk] = v;
        }
    }
    __syncwarp();
    #pragma unroll
    for (int kk=0;kk<7;kk++){
        int cc = lane + kk*32;
        if (cc < 200){
            int rc = (cc<100)? cc : cc+200;
            lin[rc] = keep[kk];
        }
    }
    fft400<false,true,false>(lin,tmp,lane);   // half-zero input: middle never read
    float4* out4 = (float4*)(g_S + ((size_t)b*200+c)*400);
    const float4* l4 = (const float4*)lin;
    for (int m4=lane;m4<200;m4+=32) out4[m4]=l4[m4];
}

// ----------------------------- CF: row IFFT -> intensity (logical layout) ----------
__global__ void kCF(){
    __shared__ __align__(16) float2 s_lin[WPB][400];
    __shared__ float2 s_tmp[WPB][421];
    int w = threadIdx.x>>5, lane = threadIdx.x&31;
    int idx = blockIdx.x*WPB + w;
    int b = idx/200, c = idx%200;
    float2* lin = s_lin[w]; float2* tmp = s_tmp[w];
    const float4* S4 = (const float4*)(g_S2 + ((size_t)b*200+c)*400);
    float4* lin4 = (float4*)lin;
    for (int m4=lane;m4<200;m4+=32) lin4[m4]=S4[m4];
    fft400<true,false,true>(lin,tmp,lane);          // cropped inverse
    int i = (c<100)? c+100 : c-100;
    float* Ib = g_I + (size_t)b*40000 + i*200;
    const float sc = 1.f/400.f;
    for (int cc=lane;cc<200;cc+=32){
        int rc = (cc<100)? cc : cc+200;
        int j  = (cc<100)? cc+100 : cc-100;
        float vx = lin[rc].x*sc, vy = lin[rc].y*sc;
        Ib[j] = vx*vx + vy*vy;
    }
}

// ----------------------------- pooling: 8x8 mean -> [p][b], p-fastest mapping ------
__global__ void kPool(){
    int idx = blockIdx.x*256 + threadIdx.x;
    if (idx >= 20000) return;
    int b = idx / 625, p = idx % 625;     // adjacent threads: adjacent p
    int mi = p/25, mj = p%25;
    const float* base = g_I + (size_t)b*40000 + mi*8*200 + mj*8;
    float s = 0.f;
    #pragma unroll
    for (int u=0;u<8;u++)
        #pragma unroll
        for (int v=0;v<8;v++) s += base[u*200+v];
    g_pool[p*32+b] = s*(1.f/64.f);
}

// ----------------------------- per-window MLP + voting -----------------------------
#define HSTR 513    // padded hid stride (bank-conflict-free)
__global__ void __launch_bounds__(256) kWin(
                     const float* __restrict__ b1, const float* __restrict__ W2,
                     const float* __restrict__ b2, const float* __restrict__ gamma,
                     const float* __restrict__ beta, float* __restrict__ out)
{
    extern __shared__ float dsm[];
    float* swin = dsm;                    // [cell][b] up to 25*32
    float* hid  = dsm + 800;              // [b][hh] 32*HSTR
    float* lg   = dsm + 800 + 32*HSTR;    // [b][o]  32*10
    __shared__ double red1[256], red2[256];
    __shared__ int   pidx[25];
    __shared__ float s_inv, s_c0;
    __shared__ int   s_a[32];
    __shared__ float s_delta[32];

    int wI = blockIdx.x;
    int i = wI/25, j = wI%25;
    int wr = min(5, 25-i), wc = min(5, 25-j);
    int cells = wr*wc;
    int tid = threadIdx.x;
    if (tid < cells) pidx[tid] = (i + tid/wc)*25 + (j + tid%wc);
    __syncthreads();

    double s1 = 0.0, s2 = 0.0;
    for (int q=tid; q<cells*32; q+=256){
        int cell = q>>5, b = q&31;
        float v = g_pool[pidx[cell]*32 + b];
        swin[q] = v;
        s1 += v; s2 += (double)v*(double)v;
    }
    red1[tid]=s1; red2[tid]=s2;
    __syncthreads();
    for (int st=128; st>0; st>>=1){
        if (tid<st){ red1[tid]+=red1[tid+st]; red2[tid]+=red2[tid+st]; }
        __syncthreads();
    }
    if (tid == 0){
        double mu  = red1[0]/20000.0;
        double var = red2[0]/20000.0 - mu*mu;
        float inv = gamma[0]/(float)sqrt(var + 1e-5);
        s_inv = inv;
        s_c0  = beta[0] - (float)mu*inv;
    }
    __syncthreads();
    float inv = s_inv, c0 = s_c0;

    // hid[b][hh] = relu(c0*R1 + inv*<win,W1win> + b1); 8 batches per thread.
    for (int it=0; it<8; it++){
        int task = it*256 + tid;          // 2048 tasks = 4 bgroups x 512 hh
        int hh = task & 511, bg = task >> 9;
        float acc[8];
        #pragma unroll
        for (int u=0;u<8;u++) acc[u]=0.f;
        for (int cell=0; cell<cells; cell++){
            float wv = g_W1T[pidx[cell]*512+hh];
            const float* sw = swin + cell*32 + bg*8;
            #pragma unroll
            for (int u=0;u<8;u++) acc[u] = fmaf(sw[u], wv, acc[u]);
        }
        float base = fmaf(c0, g_R1[hh], b1[hh]);
        #pragma unroll
        for (int u=0;u<8;u++){
            float pre = fmaf(inv, acc[u], base);
            hid[(bg*8+u)*HSTR + hh] = fmaxf(pre, 0.f);
        }
    }
    __syncthreads();

    for (int t=tid; t<320; t+=256){
        int b = t/10, oo = t%10;
        float acc = b2[oo];
        const float* hb = hid + b*HSTR;
        const float* wv = W2 + oo*512;
        for (int hh=0; hh<512; hh++) acc = fmaf(hb[hh], wv[hh], acc);
        lg[b*10+oo] = acc;
    }
    __syncthreads();

    if (tid < 32){
        int b = tid;
        float lmax = lg[b*10], lmin = lg[b*10];
        int am = 0;
        for (int oo=1;oo<10;oo++){
            float v = lg[b*10+oo];
            if (v > lmax){ lmax = v; am = oo; }
            if (v < lmin)  lmin = v;
        }
        float se = 0.f;
        for (int oo=0;oo<10;oo++) se += expf(lg[b*10+oo]-lmax);
        s_a[b] = am;
        s_delta[b] = (1.f - expf(lmin-lmax))/se;  // pmax - pmin
    }
    __syncthreads();
    if (tid == 0){
        int votes[11];
        for (int k=0;k<11;k++) votes[k]=0;
        for (int b=0;b<32;b++) votes[s_a[b]]++;
        int f0 = 0, best = votes[0];
        for (int k=1;k<11;k++) if (votes[k] > best){ best = votes[k]; f0 = k; }
        float sum = 0.f; int cnt = 0;
        for (int b=0;b<32;b++)
            if (s_a[b]==f0 && s_delta[b]!=0.f){ sum += s_delta[b]; cnt++; }
        int fin;
        if (cnt > 0){ float d1 = sum/(float)cnt; fin = (d1 < 0.2f) ? 0 : f0+1; }
        else fin = f0+1;   // delta1 = NaN; NaN < THR is false
        out[wI]       = (fin==0) ? 0.f : (float)fin;
        out[625+wI]   = (fin!=0) ? 1.f : 0.f;
        atomicAdd(&out[1250+fin], 1.0f);   // exact integer counts -> deterministic
    }
}

// ----------------------------- launch -----------------------------
extern "C" void kernel_launch(void* const* d_in, const int* in_sizes, int n_in,
                              void* d_out, int out_size)
{
    int o = (n_in >= 12 && in_sizes[1] == 1) ? 1 : 0;  // skip batch_size scalar if present
    const float*  x     = (const float*) d_in[0];
    const float2* h     = (const float2*)d_in[1+o];
    const float2* h_pro = (const float2*)d_in[2+o];
    const float2* h_det = (const float2*)d_in[3+o];
    const float*  phase = (const float*) d_in[4+o];
    const float*  W1    = (const float*) d_in[5+o];
    const float*  b1    = (const float*) d_in[6+o];
    const float*  W2    = (const float*) d_in[7+o];
    const float*  b2    = (const float*) d_in[8+o];
    const float*  gamma = (const float*) d_in[9+o];
    const float*  beta  = (const float*) d_in[10+o];
    float* out = (float*)d_out;

    cudaFuncSetAttribute(kWin, cudaFuncAttributeMaxDynamicSharedMemorySize,
                         (800 + 32*HSTR + 320)*4);

    kInit<<<1,512>>>(out);
    kPrep<<<625,256>>>(phase);
    kHT <<<dim3(13,13,3),dim3(32,8)>>>(h_pro, h, h_det);   // [0]=h_pro, [1]=h, [2]=h_det
    kT  <<<dim3(20,16),dim3(32,8)>>>(W1);
    kR1 <<<512,128>>>(W1);

    kA0 <<<1600,128>>>(x);
    kB  <<<1600,128>>>(0);                 // h_pro
    kC  <<<1600,128>>>(-1);
    for (int l=0; l<4; l++){
        kB <<<1600,128>>>(1);              // h (transposed once, reused 4x)
        kC <<<1600,128>>>(l);
    }
    kB  <<<1600,128>>>(2);                 // h_det
    kCF <<<1600,128>>>();

    kPool<<<79,256>>>();

    kWin<<<625,256,(800 + 32*HSTR + 320)*4>>>(b1, W2, b2, gamma, beta, out);
}